// round 9
// baseline (speedup 1.0000x reference)
#include <cuda_runtime.h>
#include <cuda_bf16.h>
#include <math.h>
#include <stdint.h>

#define NSEQ  8192
#define VTOK  25
#define NROWS 204800          // NSEQ * VTOK
#define DM    256
#define NH    8
#define HD    32
#define DF    1024
#define N3    768
#define LDH   264             // smem A-tile row stride (halves), conflict-free ldmatrix
#define LDQS  772             // attn smem qkv row stride (halves)

// packed bf16 fragment weights (uint32 words): [tile][kb32][lane][uint4]
#define BQ_OFF 0
#define BP_OFF 98304
#define B1_OFF 131072
#define B2_OFF 262144
#define WU32   393216

__device__ uint32_t       g_wb[WU32];
__device__ __nv_bfloat16  g_y  [(size_t)NROWS * DM];    // LN1 out
__device__ __nv_bfloat16  g_qkv[(size_t)NROWS * N3];    // qkv
__device__ __nv_bfloat16  g_att[(size_t)NROWS * DM];    // attention out
__device__ float          g_xf [(size_t)NROWS * DM];    // residual after proj (fp32)
__device__ __nv_bfloat16  g_y2 [(size_t)NROWS * DM];    // LN2 out
__device__ __nv_bfloat16  g_h  [(size_t)NROWS * DF];    // FFN hidden

__device__ __forceinline__ float gelu_exact(float v) {
    return 0.5f * v * (1.f + erff(v * 0.70710678118654752440f));
}
__device__ __forceinline__ uint32_t pack_bf2(float lo, float hi) {
    __nv_bfloat162 p;
    p.x = __float2bfloat16_rn(lo);
    p.y = __float2bfloat16_rn(hi);
    return *(uint32_t*)&p;
}

// ---- weight packing to bf16 m16n8k16 B-fragments ----
// uint4 per (tile, kb32, lane): .x={k+2t4,+1}, .y={+8,+9}, .z/.w same +16.
__global__ void prep_pack(const float* __restrict__ qkv_w, const float* __restrict__ proj_w,
                          const float* __restrict__ f1,    const float* __restrict__ f2) {
    int i = blockIdx.x * 256 + threadIdx.x;
    if (i >= WU32) return;
    int comp = i & 3, lane = (i >> 2) & 31;
    int g = lane >> 2, t4 = lane & 3;
    int klo = 2 * t4 + ((comp & 1) << 3) + ((comp >> 1) << 4);
    const float* W; int ldw, k, col;
    if (i < BP_OFF) {                         // QKV: 96 tiles x 8 kb
        int r2 = i >> 7;  int kb = r2 & 7, tile = r2 >> 3;
        col = tile * 8 + g; k = kb * 32 + klo; W = qkv_w; ldw = N3;
    } else if (i < B1_OFF) {                  // proj: 32 tiles x 8 kb
        int r2 = (i - BP_OFF) >> 7;  int kb = r2 & 7, tile = r2 >> 3;
        col = tile * 8 + g; k = kb * 32 + klo; W = proj_w; ldw = DM;
    } else if (i < B2_OFF) {                  // ffn1: 128 tiles x 8 kb
        int r2 = (i - B1_OFF) >> 7;  int kb = r2 & 7, tile = r2 >> 3;
        col = tile * 8 + g; k = kb * 32 + klo; W = f1; ldw = DF;
    } else {                                  // ffn2: 32 tiles x 32 kb (K=1024)
        int r2 = (i - B2_OFF) >> 7;  int kb = r2 & 31, tile = r2 >> 5;
        col = tile * 8 + g; k = kb * 32 + klo; W = f2; ldw = DM;
    }
    g_wb[i] = pack_bf2(W[(size_t)k * ldw + col], W[(size_t)(k + 1) * ldw + col]);
}

#define MMA_BF(D, A, B0, B1)                                                \
    asm("mma.sync.aligned.m16n8k16.row.col.f32.bf16.bf16.f32 "              \
        "{%0,%1,%2,%3}, {%4,%5,%6,%7}, {%8,%9}, {%0,%1,%2,%3};"             \
        : "+f"(D[0]), "+f"(D[1]), "+f"(D[2]), "+f"(D[3])                    \
        : "r"(A[0]), "r"(A[1]), "r"(A[2]), "r"(A[3]), "r"(B0), "r"(B1))

#define LDSM4(A, addr)                                                      \
    asm volatile("ldmatrix.sync.aligned.m8n8.x4.shared.b16 {%0,%1,%2,%3}, [%4];" \
        : "=r"(A[0]), "=r"(A[1]), "=r"(A[2]), "=r"(A[3]) : "r"(addr))

__device__ __forceinline__ uint32_t ldsm_addr(const __nv_bfloat16* base, int ldh, int lane) {
    return (uint32_t)__cvta_generic_to_shared(base + (lane & 15) * ldh + (lane >> 4) * 8);
}

// Warp computes 32 x NT*8 tile; A bf16 via ldmatrix, B packed from gmem/L2, 1-deep reg buffer.
template<int NT, int KB>
__device__ __forceinline__ void gemm_bf(uint32_t a0addr, uint32_t a1addr,
                                        const uint4* __restrict__ Bp,
                                        const int (&tadd)[NT],
                                        float (&acc)[2][NT][4], int lane)
{
    uint4 bc[NT], bn[NT];
    #pragma unroll
    for (int nt = 0; nt < NT; nt++) bc[nt] = Bp[tadd[nt] * 32 + lane];
    #pragma unroll
    for (int kb = 0; kb < KB; kb++) {
        if (kb < KB - 1) {
            #pragma unroll
            for (int nt = 0; nt < NT; nt++) bn[nt] = Bp[(tadd[nt] + kb + 1) * 32 + lane];
        }
        uint32_t A0[4], A1[4], A2[4], A3[4];
        LDSM4(A0, a0addr + kb * 64);
        LDSM4(A1, a1addr + kb * 64);
        LDSM4(A2, a0addr + kb * 64 + 32);
        LDSM4(A3, a1addr + kb * 64 + 32);
        #pragma unroll
        for (int nt = 0; nt < NT; nt++) {
            MMA_BF(acc[0][nt], A0, bc[nt].x, bc[nt].y);
            MMA_BF(acc[1][nt], A1, bc[nt].x, bc[nt].y);
            MMA_BF(acc[0][nt], A2, bc[nt].z, bc[nt].w);
            MMA_BF(acc[1][nt], A3, bc[nt].z, bc[nt].w);
        }
        if (kb < KB - 1) {
            #pragma unroll
            for (int nt = 0; nt < NT; nt++) bc[nt] = bn[nt];
        }
    }
}

// ---- LayerNorm: fp32 rows -> bf16 rows ----
__device__ __forceinline__ void ln_row_bf(const float* __restrict__ src,
                                          __nv_bfloat16* __restrict__ dst,
                                          const float* __restrict__ gg,
                                          const float* __restrict__ bb, int lane)
{
    float v[8], s = 0.f, s2 = 0.f;
    #pragma unroll
    for (int j = 0; j < 8; j++) { v[j] = src[lane + 32 * j]; s += v[j]; s2 += v[j] * v[j]; }
    #pragma unroll
    for (int o = 16; o > 0; o >>= 1) {
        s  += __shfl_xor_sync(0xffffffffu, s,  o);
        s2 += __shfl_xor_sync(0xffffffffu, s2, o);
    }
    float mean = s * (1.f / DM);
    float var  = s2 * (1.f / DM) - mean * mean;
    float inv  = rsqrtf(var + 1e-5f);
    #pragma unroll
    for (int j = 0; j < 8; j++) {
        int c = lane + 32 * j;
        dst[c] = __float2bfloat16_rn((v[j] - mean) * inv * gg[c] + bb[c]);
    }
}

__global__ __launch_bounds__(256) void ln_kernel(const float* __restrict__ src,
                                                 __nv_bfloat16* __restrict__ dst,
                                                 const float* __restrict__ gg,
                                                 const float* __restrict__ bb)
{
    int row  = blockIdx.x * 8 + (threadIdx.x >> 5);
    int lane = threadIdx.x & 31;
    ln_row_bf(src + (size_t)row * DM, dst + (size_t)row * DM, gg, bb, lane);
}

// ---- A-tile loader: 128 rows x 256 bf16 cols from global (row stride srow) ----
__device__ __forceinline__ void load_atile(const __nv_bfloat16* __restrict__ Ag,
                                           size_t row0, int srow, int c0,
                                           __nv_bfloat16* __restrict__ sA, int tid)
{
    #pragma unroll
    for (int i = 0; i < 16; i++) {
        int idx = tid + i * 256;
        int row = idx >> 5, c8 = idx & 31;
        *(uint4*)(sA + row * LDH + c8 * 8) =
            *(const uint4*)(Ag + (row0 + row) * srow + c0 + c8 * 8);
    }
}

#define GEMM_PRO()                                                          \
    extern __shared__ __nv_bfloat16 sA[];                                   \
    const int tid = threadIdx.x, lane = tid & 31;                           \
    const int wid = tid >> 5, wm = wid >> 1, wn = wid & 1;                  \
    const int g = lane >> 2, t4 = lane & 3;                                 \
    const int ntblk = blockIdx.x;                                           \
    const size_t mb = (size_t)blockIdx.y * 128;                             \
    float acc[2][4][4];                                                     \
    _Pragma("unroll") for (int mt = 0; mt < 2; mt++)                        \
    _Pragma("unroll") for (int nt = 0; nt < 4; nt++)                        \
    _Pragma("unroll") for (int e = 0; e < 4; e++) acc[mt][nt][e] = 0.f;

// ---- QKV GEMM: g_y @ qkv_w + b -> g_qkv (bf16). grid (12, 1600) ----
__global__ __launch_bounds__(256, 2) void k_qkv(const float* __restrict__ bias)
{
    GEMM_PRO();
    load_atile(g_y, mb, DM, 0, sA, tid);
    __syncthreads();
    uint32_t a0 = ldsm_addr(sA + (wm * 32) * LDH, LDH, lane), a1 = a0 + 16 * LDH * 2;
    int tadd[4];
    #pragma unroll
    for (int nt = 0; nt < 4; nt++) tadd[nt] = (ntblk * 8 + wn * 4 + nt) * 8;
    gemm_bf<4, 8>(a0, a1, (const uint4*)g_wb + BQ_OFF / 4, tadd, acc, lane);
    const int cb = ntblk * 64 + wn * 32;
    #pragma unroll
    for (int mt = 0; mt < 2; mt++)
        #pragma unroll
        for (int nt = 0; nt < 4; nt++) {
            int c = cb + nt * 8 + 2 * t4;
            float b0 = bias[c], b1 = bias[c + 1];
            #pragma unroll
            for (int hrow = 0; hrow < 2; hrow++) {
                size_t R = mb + wm * 32 + mt * 16 + g + hrow * 8;
                *(uint32_t*)(g_qkv + R * N3 + c) =
                    pack_bf2(acc[mt][nt][2 * hrow] + b0, acc[mt][nt][2 * hrow + 1] + b1);
            }
        }
}

// ---- attention: per-sequence, warp = head ----
__global__ __launch_bounds__(256) void attn_kernel(const float* __restrict__ logit_scale)
{
    __shared__ __nv_bfloat16 sq[VTOK * LDQS];
    const int tid = threadIdx.x, lane = tid & 31, h = tid >> 5;
    const size_t seq = blockIdx.x;
    const size_t base = seq * VTOK * (size_t)N3;

    // load 25x768 bf16 -> smem (uint2 = 4 halves)
    for (int i = 0; i < 19; i++) {
        int idx = tid + i * 256;
        if (idx < VTOK * (N3 / 4)) {
            int row = idx / (N3 / 4), c4 = idx % (N3 / 4);
            *(uint2*)(sq + row * LDQS + c4 * 4) = *(const uint2*)(g_qkv + base + row * N3 + c4 * 4);
        }
    }
    __syncthreads();

    const int i  = lane;
    const int ri = (i < VTOK) ? i : 0;
    const __nv_bfloat16* qb = sq + h * HD;
    const __nv_bfloat16* kb = sq + DM + h * HD;
    const __nv_bfloat16* vb = sq + 2 * DM + h * HD;

    float q[HD];
    #pragma unroll
    for (int d = 0; d < HD; d++) q[d] = __bfloat162float(qb[ri * LDQS + d]);
    float qn2 = 0.f, kn2 = 0.f;
    #pragma unroll
    for (int d = 0; d < HD; d++) qn2 = fmaf(q[d], q[d], qn2);
    #pragma unroll
    for (int d = 0; d < HD; d++) {
        float kv = __bfloat162float(kb[ri * LDQS + d]);
        kn2 = fmaf(kv, kv, kn2);
    }
    float inv_kn = 1.f / fmaxf(sqrtf(kn2), 1e-12f);

    float sc   = expf(fminf(logit_scale[h], 4.6051701859880913680f));
    float coef = sc * (1.f / fmaxf(sqrtf(qn2), 1e-12f)) * 0.17677669529663688110f;

    float lg[VTOK];
    #pragma unroll
    for (int j = 0; j < VTOK; j++) {
        float ikn = __shfl_sync(0xffffffffu, inv_kn, j);
        float dot = 0.f;
        #pragma unroll
        for (int d = 0; d < HD; d++) dot = fmaf(q[d], __bfloat162float(kb[j * LDQS + d]), dot);
        lg[j] = dot * coef * ikn;
    }
    float m = lg[0];
    #pragma unroll
    for (int j = 1; j < VTOK; j++) m = fmaxf(m, lg[j]);
    float ssum = 0.f;
    #pragma unroll
    for (int j = 0; j < VTOK; j++) { lg[j] = expf(lg[j] - m); ssum += lg[j]; }
    float rs = 1.f / ssum;

    float o[HD];
    #pragma unroll
    for (int d = 0; d < HD; d++) o[d] = 0.f;
    #pragma unroll
    for (int j = 0; j < VTOK; j++) {
        float p = lg[j] * rs;
        #pragma unroll
        for (int d = 0; d < HD; d++) o[d] = fmaf(p, __bfloat162float(vb[j * LDQS + d]), o[d]);
    }
    if (i < VTOK) {
        __nv_bfloat16* og = g_att + (seq * VTOK + i) * DM + h * HD;
        #pragma unroll
        for (int d = 0; d < HD; d += 2)
            *(uint32_t*)(og + d) = pack_bf2(o[d], o[d + 1]);
    }
}

// ---- proj GEMM + residual: g_att @ proj_w + b + x -> g_xf (fp32). grid (4, 1600) ----
__global__ __launch_bounds__(256, 2) void k_proj(const float* __restrict__ x,
                                                 const float* __restrict__ bias)
{
    GEMM_PRO();
    load_atile(g_att, mb, DM, 0, sA, tid);
    __syncthreads();
    uint32_t a0 = ldsm_addr(sA + (wm * 32) * LDH, LDH, lane), a1 = a0 + 16 * LDH * 2;
    int tadd[4];
    #pragma unroll
    for (int nt = 0; nt < 4; nt++) tadd[nt] = (ntblk * 8 + wn * 4 + nt) * 8;
    gemm_bf<4, 8>(a0, a1, (const uint4*)g_wb + BP_OFF / 4, tadd, acc, lane);
    const int cb = ntblk * 64 + wn * 32;
    #pragma unroll
    for (int mt = 0; mt < 2; mt++)
        #pragma unroll
        for (int nt = 0; nt < 4; nt++) {
            int c = cb + nt * 8 + 2 * t4;
            float b0 = bias[c], b1 = bias[c + 1];
            #pragma unroll
            for (int hrow = 0; hrow < 2; hrow++) {
                size_t R = mb + wm * 32 + mt * 16 + g + hrow * 8;
                float2 xv = *(const float2*)(x + R * DM + c);
                float2 o;
                o.x = xv.x + acc[mt][nt][2 * hrow]     + b0;
                o.y = xv.y + acc[mt][nt][2 * hrow + 1] + b1;
                *(float2*)(g_xf + R * DM + c) = o;
            }
        }
}

// ---- FFN1 GEMM + gelu: g_y2 @ ffn_w1 + b -> g_h (bf16). grid (16, 1600) ----
__global__ __launch_bounds__(256, 2) void k_ffn1(const float* __restrict__ bias)
{
    GEMM_PRO();
    load_atile(g_y2, mb, DM, 0, sA, tid);
    __syncthreads();
    uint32_t a0 = ldsm_addr(sA + (wm * 32) * LDH, LDH, lane), a1 = a0 + 16 * LDH * 2;
    int tadd[4];
    #pragma unroll
    for (int nt = 0; nt < 4; nt++) tadd[nt] = (ntblk * 8 + wn * 4 + nt) * 8;
    gemm_bf<4, 8>(a0, a1, (const uint4*)g_wb + B1_OFF / 4, tadd, acc, lane);
    const int cb = ntblk * 64 + wn * 32;
    #pragma unroll
    for (int mt = 0; mt < 2; mt++)
        #pragma unroll
        for (int nt = 0; nt < 4; nt++) {
            int c = cb + nt * 8 + 2 * t4;
            float b0 = bias[c], b1 = bias[c + 1];
            #pragma unroll
            for (int hrow = 0; hrow < 2; hrow++) {
                size_t R = mb + wm * 32 + mt * 16 + g + hrow * 8;
                *(uint32_t*)(g_h + R * DF + c) =
                    pack_bf2(gelu_exact(acc[mt][nt][2 * hrow] + b0),
                             gelu_exact(acc[mt][nt][2 * hrow + 1] + b1));
            }
        }
}

// ---- FFN2 GEMM + residual: g_h @ ffn_w2 + b + g_xf -> out (fp32). grid (4, 1600) ----
__global__ __launch_bounds__(256, 2) void k_ffn2(const float* __restrict__ bias,
                                                 float* __restrict__ out)
{
    GEMM_PRO();
    uint32_t a0 = ldsm_addr(sA + (wm * 32) * LDH, LDH, lane), a1 = a0 + 16 * LDH * 2;
    #pragma unroll
    for (int ch = 0; ch < 4; ch++) {
        if (ch) __syncthreads();
        load_atile(g_h, mb, DF, ch * 256, sA, tid);
        __syncthreads();
        int tadd[4];
        #pragma unroll
        for (int nt = 0; nt < 4; nt++)
            tadd[nt] = (ntblk * 8 + wn * 4 + nt) * 32 + ch * 8;
        gemm_bf<4, 8>(a0, a1, (const uint4*)g_wb + B2_OFF / 4, tadd, acc, lane);
    }
    const int cb = ntblk * 64 + wn * 32;
    #pragma unroll
    for (int mt = 0; mt < 2; mt++)
        #pragma unroll
        for (int nt = 0; nt < 4; nt++) {
            int c = cb + nt * 8 + 2 * t4;
            float b0 = bias[c], b1 = bias[c + 1];
            #pragma unroll
            for (int hrow = 0; hrow < 2; hrow++) {
                size_t R = mb + wm * 32 + mt * 16 + g + hrow * 8;
                float2 xv = *(const float2*)(g_xf + R * DM + c);
                float2 o;
                o.x = xv.x + acc[mt][nt][2 * hrow]     + b0;
                o.y = xv.y + acc[mt][nt][2 * hrow + 1] + b1;
                *(float2*)(out + R * DM + c) = o;
            }
        }
}

extern "C" void kernel_launch(void* const* d_in, const int* in_sizes, int n_in,
                              void* d_out, int out_size)
{
    const float* x      = (const float*)d_in[0];
    const float* ln1_g  = (const float*)d_in[1];
    const float* ln1_b  = (const float*)d_in[2];
    const float* qkv_w  = (const float*)d_in[3];
    const float* qkv_b  = (const float*)d_in[4];
    const float* proj_w = (const float*)d_in[5];
    const float* proj_b = (const float*)d_in[6];
    const float* lscale = (const float*)d_in[7];
    const float* ln2_g  = (const float*)d_in[8];
    const float* ln2_b  = (const float*)d_in[9];
    const float* ffn_w1 = (const float*)d_in[10];
    const float* ffn_b1 = (const float*)d_in[11];
    const float* ffn_w2 = (const float*)d_in[12];
    const float* ffn_b2 = (const float*)d_in[13];
    float* out = (float*)d_out;

    __nv_bfloat16 *gy, *gy2;
    cudaGetSymbolAddress((void**)&gy,  g_y);
    cudaGetSymbolAddress((void**)&gy2, g_y2);
    float* gxf;
    cudaGetSymbolAddress((void**)&gxf, g_xf);

    const int smA = 128 * LDH * 2;   // 67584 B
    cudaFuncSetAttribute(k_qkv,  cudaFuncAttributeMaxDynamicSharedMemorySize, smA);
    cudaFuncSetAttribute(k_proj, cudaFuncAttributeMaxDynamicSharedMemorySize, smA);
    cudaFuncSetAttribute(k_ffn1, cudaFuncAttributeMaxDynamicSharedMemorySize, smA);
    cudaFuncSetAttribute(k_ffn2, cudaFuncAttributeMaxDynamicSharedMemorySize, smA);

    prep_pack<<<(WU32 + 255) / 256, 256>>>(qkv_w, proj_w, ffn_w1, ffn_w2);
    ln_kernel<<<NROWS / 8, 256>>>(x, gy, ln1_g, ln1_b);
    k_qkv <<<dim3(12, 1600), 256, smA>>>(qkv_b);
    attn_kernel<<<NSEQ, 256>>>(lscale);
    k_proj<<<dim3(4, 1600), 256, smA>>>(x, proj_b);
    ln_kernel<<<NROWS / 8, 256>>>(gxf, gy2, ln2_g, ln2_b);
    k_ffn1<<<dim3(16, 1600), 256, smA>>>(ffn_b1);
    k_ffn2<<<dim3(4, 1600), 256, smA>>>(ffn_b2, out);
}

// round 10
// speedup vs baseline: 1.7465x; 1.7465x over previous
#include <cuda_runtime.h>
#include <cuda_bf16.h>
#include <math.h>
#include <stdint.h>

#define NSEQ  8192
#define VTOK  25
#define NROWS 204800          // NSEQ * VTOK
#define DM    256
#define NH    8
#define HD    32
#define DF    1024
#define N3    768
#define LDH   264             // smem A-tile row stride (halves), conflict-free ldmatrix
#define LDQS  772             // attn smem qkv row stride (floats)

// packed bf16 fragment weights (uint32 words): [tile][kb32][lane][uint4]
#define BQ_OFF 0
#define BP_OFF 98304
#define B1_OFF 131072
#define B2_OFF 262144
#define WU32   393216

__device__ uint32_t       g_wb[WU32];
__device__ __nv_bfloat16  g_y  [(size_t)NROWS * DM];    // LN1 out
__device__ float          g_qkv[(size_t)NROWS * N3];    // qkv (fp32 — attn is sole consumer)
__device__ __nv_bfloat16  g_att[(size_t)NROWS * DM];    // attention out
__device__ float          g_xf [(size_t)NROWS * DM];    // residual after proj (fp32)
__device__ __nv_bfloat16  g_y2 [(size_t)NROWS * DM];    // LN2 out
__device__ __nv_bfloat16  g_h  [(size_t)NROWS * DF];    // FFN hidden

__device__ __forceinline__ float gelu_exact(float v) {
    return 0.5f * v * (1.f + erff(v * 0.70710678118654752440f));
}
__device__ __forceinline__ uint32_t pack_bf2(float lo, float hi) {
    __nv_bfloat162 p;
    p.x = __float2bfloat16_rn(lo);
    p.y = __float2bfloat16_rn(hi);
    return *(uint32_t*)&p;
}

// ---- packed f32x2 helpers (FFMA2 path, PTX-only) ----
__device__ __forceinline__ void fma2(uint64_t& d, uint64_t a, uint64_t b) {
    asm("fma.rn.f32x2 %0, %1, %2, %0;" : "+l"(d) : "l"(a), "l"(b));
}
__device__ __forceinline__ uint64_t fpack2(float x, float y) {
    uint64_t r; asm("mov.b64 %0, {%1,%2};" : "=l"(r) : "f"(x), "f"(y)); return r;
}
__device__ __forceinline__ float2 funpack2(uint64_t v) {
    float2 f; asm("mov.b64 {%0,%1}, %2;" : "=f"(f.x), "=f"(f.y) : "l"(v)); return f;
}

// ---- weight packing to bf16 m16n8k16 B-fragments ----
__global__ void prep_pack(const float* __restrict__ qkv_w, const float* __restrict__ proj_w,
                          const float* __restrict__ f1,    const float* __restrict__ f2) {
    int i = blockIdx.x * 256 + threadIdx.x;
    if (i >= WU32) return;
    int comp = i & 3, lane = (i >> 2) & 31;
    int g = lane >> 2, t4 = lane & 3;
    int klo = 2 * t4 + ((comp & 1) << 3) + ((comp >> 1) << 4);
    const float* W; int ldw, k, col;
    if (i < BP_OFF) {                         // QKV: 96 tiles x 8 kb
        int r2 = i >> 7;  int kb = r2 & 7, tile = r2 >> 3;
        col = tile * 8 + g; k = kb * 32 + klo; W = qkv_w; ldw = N3;
    } else if (i < B1_OFF) {                  // proj: 32 tiles x 8 kb
        int r2 = (i - BP_OFF) >> 7;  int kb = r2 & 7, tile = r2 >> 3;
        col = tile * 8 + g; k = kb * 32 + klo; W = proj_w; ldw = DM;
    } else if (i < B2_OFF) {                  // ffn1: 128 tiles x 8 kb
        int r2 = (i - B1_OFF) >> 7;  int kb = r2 & 7, tile = r2 >> 3;
        col = tile * 8 + g; k = kb * 32 + klo; W = f1; ldw = DF;
    } else {                                  // ffn2: 32 tiles x 32 kb (K=1024)
        int r2 = (i - B2_OFF) >> 7;  int kb = r2 & 31, tile = r2 >> 5;
        col = tile * 8 + g; k = kb * 32 + klo; W = f2; ldw = DM;
    }
    g_wb[i] = pack_bf2(W[(size_t)k * ldw + col], W[(size_t)(k + 1) * ldw + col]);
}

#define MMA_BF(D, A, B0, B1)                                                \
    asm("mma.sync.aligned.m16n8k16.row.col.f32.bf16.bf16.f32 "              \
        "{%0,%1,%2,%3}, {%4,%5,%6,%7}, {%8,%9}, {%0,%1,%2,%3};"             \
        : "+f"(D[0]), "+f"(D[1]), "+f"(D[2]), "+f"(D[3])                    \
        : "r"(A[0]), "r"(A[1]), "r"(A[2]), "r"(A[3]), "r"(B0), "r"(B1))

#define LDSM4(A, addr)                                                      \
    asm volatile("ldmatrix.sync.aligned.m8n8.x4.shared.b16 {%0,%1,%2,%3}, [%4];" \
        : "=r"(A[0]), "=r"(A[1]), "=r"(A[2]), "=r"(A[3]) : "r"(addr))

#define LDS128U(r0, r1, r2, r3, addr)                                       \
    asm volatile("ld.shared.v4.u32 {%0,%1,%2,%3}, [%4];"                    \
        : "=r"(r0), "=r"(r1), "=r"(r2), "=r"(r3) : "r"(addr))

__device__ __forceinline__ void cp_async16(uint32_t saddr, const void* g) {
    asm volatile("cp.async.cg.shared.global [%0], [%1], 16;" :: "r"(saddr), "l"(g) : "memory");
}
#define CP_COMMIT() asm volatile("cp.async.commit_group;" ::: "memory")
#define CP_WAIT0()  asm volatile("cp.async.wait_group 0;" ::: "memory")

__device__ __forceinline__ uint32_t ldsm_addr(const __nv_bfloat16* base, int ldh, int lane) {
    return (uint32_t)__cvta_generic_to_shared(base + (lane & 15) * ldh + (lane >> 4) * 8);
}

// Warp computes 32 x NT*8 tile; A via ldmatrix, B fragments from smem (LDS.128).
template<int NT, int KB>
__device__ __forceinline__ void gemm_sm(uint32_t a0addr, uint32_t a1addr,
                                        uint32_t sBaddr,      // smem byte addr of B frags
                                        int tbase,            // local tile base (wn*NT)
                                        float (&acc)[2][NT][4], int lane)
{
    #pragma unroll
    for (int kb = 0; kb < KB; kb++) {
        uint32_t A0[4], A1[4], A2[4], A3[4];
        LDSM4(A0, a0addr + kb * 64);
        LDSM4(A1, a1addr + kb * 64);
        LDSM4(A2, a0addr + kb * 64 + 32);
        LDSM4(A3, a1addr + kb * 64 + 32);
        #pragma unroll
        for (int nt = 0; nt < NT; nt++) {
            uint32_t b0, b1, b2, b3;
            LDS128U(b0, b1, b2, b3, sBaddr + (((tbase + nt) * KB + kb) * 32 + lane) * 16);
            MMA_BF(acc[0][nt], A0, b0, b1);
            MMA_BF(acc[1][nt], A1, b0, b1);
            MMA_BF(acc[0][nt], A2, b2, b3);
            MMA_BF(acc[1][nt], A3, b2, b3);
        }
    }
}

// ---- LayerNorm: fp32 rows -> bf16 rows ----
__device__ __forceinline__ void ln_row_bf(const float* __restrict__ src,
                                          __nv_bfloat16* __restrict__ dst,
                                          const float* __restrict__ gg,
                                          const float* __restrict__ bb, int lane)
{
    float v[8], s = 0.f, s2 = 0.f;
    #pragma unroll
    for (int j = 0; j < 8; j++) { v[j] = src[lane + 32 * j]; s += v[j]; s2 += v[j] * v[j]; }
    #pragma unroll
    for (int o = 16; o > 0; o >>= 1) {
        s  += __shfl_xor_sync(0xffffffffu, s,  o);
        s2 += __shfl_xor_sync(0xffffffffu, s2, o);
    }
    float mean = s * (1.f / DM);
    float var  = s2 * (1.f / DM) - mean * mean;
    float inv  = rsqrtf(var + 1e-5f);
    #pragma unroll
    for (int j = 0; j < 8; j++) {
        int c = lane + 32 * j;
        dst[c] = __float2bfloat16_rn((v[j] - mean) * inv * gg[c] + bb[c]);
    }
}

__global__ __launch_bounds__(256) void ln_kernel(const float* __restrict__ src,
                                                 __nv_bfloat16* __restrict__ dst,
                                                 const float* __restrict__ gg,
                                                 const float* __restrict__ bb)
{
    int row  = blockIdx.x * 8 + (threadIdx.x >> 5);
    int lane = threadIdx.x & 31;
    ln_row_bf(src + (size_t)row * DM, dst + (size_t)row * DM, gg, bb, lane);
}

// ---- A-tile async loader: 128 rows x 256 bf16 cols (row stride srow halves) ----
__device__ __forceinline__ void load_atile_async(const __nv_bfloat16* __restrict__ Ag,
                                                 size_t row0, int srow, int c0,
                                                 __nv_bfloat16* __restrict__ sA, int tid)
{
    uint32_t sbase = (uint32_t)__cvta_generic_to_shared(sA);
    #pragma unroll
    for (int i = 0; i < 16; i++) {
        int idx = tid + i * 256;
        int row = idx >> 5, c8 = idx & 31;
        cp_async16(sbase + (row * LDH + c8 * 8) * 2,
                   Ag + (row0 + row) * (size_t)srow + c0 + c8 * 8);
    }
}

// ---- B-tile async loader: NTILE tiles x KB kb (256 uint4 per 8kb-chunk per tile) ----
__device__ __forceinline__ void load_btile_async(const uint4* __restrict__ Bg_chunkbase,
                                                 int tile_stride_u4,   // uint4 per tile
                                                 uint32_t sBaddr, int tid)
{
    #pragma unroll
    for (int t = 0; t < 8; t++) {
        cp_async16(sBaddr + (t * 256 + tid) * 16,
                   Bg_chunkbase + (size_t)t * tile_stride_u4 + tid);
    }
}

#define SM_A_BYTES 67584
#define SM_B_BYTES 32768

#define GEMM_PRO()                                                          \
    extern __shared__ __nv_bfloat16 sA[];                                   \
    uint32_t sBaddr = (uint32_t)__cvta_generic_to_shared(sA) + SM_A_BYTES;  \
    const int tid = threadIdx.x, lane = tid & 31;                           \
    const int wid = tid >> 5, wm = wid >> 1, wn = wid & 1;                  \
    const int g = lane >> 2, t4 = lane & 3;                                 \
    const int ntblk = blockIdx.x;                                           \
    const size_t mb = (size_t)blockIdx.y * 128;                             \
    float acc[2][4][4];                                                     \
    _Pragma("unroll") for (int mt = 0; mt < 2; mt++)                        \
    _Pragma("unroll") for (int nt = 0; nt < 4; nt++)                        \
    _Pragma("unroll") for (int e = 0; e < 4; e++) acc[mt][nt][e] = 0.f;

// ---- QKV GEMM: g_y @ qkv_w + b -> g_qkv (fp32). grid (12, 1600) ----
__global__ __launch_bounds__(256, 2) void k_qkv(const float* __restrict__ bias)
{
    GEMM_PRO();
    load_atile_async(g_y, mb, DM, 0, sA, tid);
    load_btile_async((const uint4*)g_wb + BQ_OFF / 4 + (size_t)ntblk * 2048, 256, sBaddr, tid);
    CP_COMMIT(); CP_WAIT0();
    __syncthreads();
    uint32_t a0 = ldsm_addr(sA + (wm * 32) * LDH, LDH, lane), a1 = a0 + 16 * LDH * 2;
    gemm_sm<4, 8>(a0, a1, sBaddr, wn * 4, acc, lane);
    const int cb = ntblk * 64 + wn * 32;
    #pragma unroll
    for (int mt = 0; mt < 2; mt++)
        #pragma unroll
        for (int nt = 0; nt < 4; nt++) {
            int c = cb + nt * 8 + 2 * t4;
            float b0 = bias[c], b1 = bias[c + 1];
            #pragma unroll
            for (int hrow = 0; hrow < 2; hrow++) {
                size_t R = mb + wm * 32 + mt * 16 + g + hrow * 8;
                float2 o;
                o.x = acc[mt][nt][2 * hrow]     + b0;
                o.y = acc[mt][nt][2 * hrow + 1] + b1;
                *(float2*)(g_qkv + R * N3 + c) = o;
            }
        }
}

// ---- attention: block = sequence, warp = head; fp32 smem + f32x2 math ----
__global__ __launch_bounds__(256) void attn_kernel(const float* __restrict__ logit_scale)
{
    extern __shared__ float sq[];
    const int tid = threadIdx.x, lane = tid & 31, h = tid >> 5;
    const size_t seq = blockIdx.x;
    const float* src = g_qkv + seq * VTOK * (size_t)N3;

    // stage 25 x 768 fp32 -> smem (float4)
    #pragma unroll
    for (int i = 0; i < 19; i++) {
        int idx = tid + i * 256;
        if (idx < VTOK * (N3 / 4)) {
            int row = idx / (N3 / 4), c4 = idx % (N3 / 4);
            *(float4*)(sq + row * LDQS + c4 * 4) = *(const float4*)(src + row * N3 + c4 * 4);
        }
    }
    __syncthreads();

    const int i  = lane;
    const int ri = (i < VTOK) ? i : 0;
    const float* qb = sq + h * HD;
    const float* kb = sq + DM + h * HD;
    const float* vb = sq + 2 * DM + h * HD;

    // q row (16 packed f32x2) + q norm
    uint64_t q2[16];
    {
        const ulonglong2* qr = (const ulonglong2*)(qb + ri * LDQS);
        #pragma unroll
        for (int p = 0; p < 8; p++) { ulonglong2 v = qr[p]; q2[2*p] = v.x; q2[2*p+1] = v.y; }
    }
    uint64_t qa = 0;
    #pragma unroll
    for (int p = 0; p < 16; p++) fma2(qa, q2[p], q2[p]);
    float2 qf = funpack2(qa);
    float qn2 = qf.x + qf.y;

    // own k row norm
    uint64_t ka = 0;
    {
        const ulonglong2* kr = (const ulonglong2*)(kb + ri * LDQS);
        #pragma unroll
        for (int p = 0; p < 8; p++) { ulonglong2 v = kr[p]; fma2(ka, v.x, v.x); fma2(ka, v.y, v.y); }
    }
    float2 kf = funpack2(ka);
    float inv_kn = 1.f / fmaxf(sqrtf(kf.x + kf.y), 1e-12f);

    float sc   = expf(fminf(logit_scale[h], 4.6051701859880913680f));
    float coef = sc * (1.f / fmaxf(sqrtf(qn2), 1e-12f)) * 0.17677669529663688110f;

    float lg[VTOK];
    #pragma unroll
    for (int j = 0; j < VTOK; j++) {
        float ikn = __shfl_sync(0xffffffffu, inv_kn, j);
        const ulonglong2* kr = (const ulonglong2*)(kb + j * LDQS);   // broadcast
        uint64_t a2 = 0;
        #pragma unroll
        for (int p = 0; p < 8; p++) {
            ulonglong2 v = kr[p];
            fma2(a2, q2[2*p], v.x);
            fma2(a2, q2[2*p+1], v.y);
        }
        float2 d = funpack2(a2);
        lg[j] = (d.x + d.y) * coef * ikn;
    }
    float m = lg[0];
    #pragma unroll
    for (int j = 1; j < VTOK; j++) m = fmaxf(m, lg[j]);
    float ssum = 0.f;
    #pragma unroll
    for (int j = 0; j < VTOK; j++) { lg[j] = expf(lg[j] - m); ssum += lg[j]; }
    float rs = 1.f / ssum;

    uint64_t o2[16];
    #pragma unroll
    for (int p = 0; p < 16; p++) o2[p] = 0;
    #pragma unroll
    for (int j = 0; j < VTOK; j++) {
        float p = lg[j] * rs;
        uint64_t p2 = fpack2(p, p);
        const ulonglong2* vr = (const ulonglong2*)(vb + j * LDQS);   // broadcast
        #pragma unroll
        for (int q = 0; q < 8; q++) {
            ulonglong2 v = vr[q];
            fma2(o2[2*q], p2, v.x);
            fma2(o2[2*q+1], p2, v.y);
        }
    }
    if (i < VTOK) {
        __nv_bfloat16* og = g_att + (seq * VTOK + i) * DM + h * HD;
        #pragma unroll
        for (int p = 0; p < 16; p++) {
            float2 f = funpack2(o2[p]);
            *(uint32_t*)(og + 2 * p) = pack_bf2(f.x, f.y);
        }
    }
}

// ---- proj GEMM + residual: g_att @ proj_w + b + x -> g_xf (fp32). grid (4, 1600) ----
__global__ __launch_bounds__(256, 2) void k_proj(const float* __restrict__ x,
                                                 const float* __restrict__ bias)
{
    GEMM_PRO();
    load_atile_async(g_att, mb, DM, 0, sA, tid);
    load_btile_async((const uint4*)g_wb + BP_OFF / 4 + (size_t)ntblk * 2048, 256, sBaddr, tid);
    CP_COMMIT(); CP_WAIT0();
    __syncthreads();
    uint32_t a0 = ldsm_addr(sA + (wm * 32) * LDH, LDH, lane), a1 = a0 + 16 * LDH * 2;
    gemm_sm<4, 8>(a0, a1, sBaddr, wn * 4, acc, lane);
    const int cb = ntblk * 64 + wn * 32;
    #pragma unroll
    for (int mt = 0; mt < 2; mt++)
        #pragma unroll
        for (int nt = 0; nt < 4; nt++) {
            int c = cb + nt * 8 + 2 * t4;
            float b0 = bias[c], b1 = bias[c + 1];
            #pragma unroll
            for (int hrow = 0; hrow < 2; hrow++) {
                size_t R = mb + wm * 32 + mt * 16 + g + hrow * 8;
                float2 xv = *(const float2*)(x + R * DM + c);
                float2 o;
                o.x = xv.x + acc[mt][nt][2 * hrow]     + b0;
                o.y = xv.y + acc[mt][nt][2 * hrow + 1] + b1;
                *(float2*)(g_xf + R * DM + c) = o;
            }
        }
}

// ---- FFN1 GEMM + gelu: g_y2 @ ffn_w1 + b -> g_h (bf16). grid (16, 1600) ----
__global__ __launch_bounds__(256, 2) void k_ffn1(const float* __restrict__ bias)
{
    GEMM_PRO();
    load_atile_async(g_y2, mb, DM, 0, sA, tid);
    load_btile_async((const uint4*)g_wb + B1_OFF / 4 + (size_t)ntblk * 2048, 256, sBaddr, tid);
    CP_COMMIT(); CP_WAIT0();
    __syncthreads();
    uint32_t a0 = ldsm_addr(sA + (wm * 32) * LDH, LDH, lane), a1 = a0 + 16 * LDH * 2;
    gemm_sm<4, 8>(a0, a1, sBaddr, wn * 4, acc, lane);
    const int cb = ntblk * 64 + wn * 32;
    #pragma unroll
    for (int mt = 0; mt < 2; mt++)
        #pragma unroll
        for (int nt = 0; nt < 4; nt++) {
            int c = cb + nt * 8 + 2 * t4;
            float b0 = bias[c], b1 = bias[c + 1];
            #pragma unroll
            for (int hrow = 0; hrow < 2; hrow++) {
                size_t R = mb + wm * 32 + mt * 16 + g + hrow * 8;
                *(uint32_t*)(g_h + R * DF + c) =
                    pack_bf2(gelu_exact(acc[mt][nt][2 * hrow] + b0),
                             gelu_exact(acc[mt][nt][2 * hrow + 1] + b1));
            }
        }
}

// ---- FFN2 GEMM + residual: g_h @ ffn_w2 + b + g_xf -> out (fp32). grid (4, 1600) ----
__global__ __launch_bounds__(256, 2) void k_ffn2(const float* __restrict__ bias,
                                                 float* __restrict__ out)
{
    GEMM_PRO();
    uint32_t a0 = ldsm_addr(sA + (wm * 32) * LDH, LDH, lane), a1 = a0 + 16 * LDH * 2;
    #pragma unroll
    for (int ch = 0; ch < 4; ch++) {
        if (ch) __syncthreads();
        load_atile_async(g_h, mb, DF, ch * 256, sA, tid);
        // per tile: chunk ch = 256 uint4 at offset ch*256 within tile's 1024
        {
            const uint4* bsrc = (const uint4*)g_wb + B2_OFF / 4
                              + (size_t)ntblk * 8 * 1024 + ch * 256;
            load_btile_async(bsrc, 1024, sBaddr, tid);
        }
        CP_COMMIT(); CP_WAIT0();
        __syncthreads();
        gemm_sm<4, 8>(a0, a1, sBaddr, wn * 4, acc, lane);
    }
    const int cb = ntblk * 64 + wn * 32;
    #pragma unroll
    for (int mt = 0; mt < 2; mt++)
        #pragma unroll
        for (int nt = 0; nt < 4; nt++) {
            int c = cb + nt * 8 + 2 * t4;
            float b0 = bias[c], b1 = bias[c + 1];
            #pragma unroll
            for (int hrow = 0; hrow < 2; hrow++) {
                size_t R = mb + wm * 32 + mt * 16 + g + hrow * 8;
                float2 xv = *(const float2*)(g_xf + R * DM + c);
                float2 o;
                o.x = xv.x + acc[mt][nt][2 * hrow]     + b0;
                o.y = xv.y + acc[mt][nt][2 * hrow + 1] + b1;
                *(float2*)(out + R * DM + c) = o;
            }
        }
}

extern "C" void kernel_launch(void* const* d_in, const int* in_sizes, int n_in,
                              void* d_out, int out_size)
{
    const float* x      = (const float*)d_in[0];
    const float* ln1_g  = (const float*)d_in[1];
    const float* ln1_b  = (const float*)d_in[2];
    const float* qkv_w  = (const float*)d_in[3];
    const float* qkv_b  = (const float*)d_in[4];
    const float* proj_w = (const float*)d_in[5];
    const float* proj_b = (const float*)d_in[6];
    const float* lscale = (const float*)d_in[7];
    const float* ln2_g  = (const float*)d_in[8];
    const float* ln2_b  = (const float*)d_in[9];
    const float* ffn_w1 = (const float*)d_in[10];
    const float* ffn_b1 = (const float*)d_in[11];
    const float* ffn_w2 = (const float*)d_in[12];
    const float* ffn_b2 = (const float*)d_in[13];
    float* out = (float*)d_out;

    __nv_bfloat16 *gy, *gy2;
    cudaGetSymbolAddress((void**)&gy,  g_y);
    cudaGetSymbolAddress((void**)&gy2, g_y2);
    float* gxf;
    cudaGetSymbolAddress((void**)&gxf, g_xf);

    const int smG = SM_A_BYTES + SM_B_BYTES;        // 100352
    const int smQ = VTOK * LDQS * 4;                // 77200 (attn)
    cudaFuncSetAttribute(k_qkv,  cudaFuncAttributeMaxDynamicSharedMemorySize, smG);
    cudaFuncSetAttribute(k_proj, cudaFuncAttributeMaxDynamicSharedMemorySize, smG);
    cudaFuncSetAttribute(k_ffn1, cudaFuncAttributeMaxDynamicSharedMemorySize, smG);
    cudaFuncSetAttribute(k_ffn2, cudaFuncAttributeMaxDynamicSharedMemorySize, smG);
    cudaFuncSetAttribute(attn_kernel, cudaFuncAttributeMaxDynamicSharedMemorySize, smQ);

    prep_pack<<<(WU32 + 255) / 256, 256>>>(qkv_w, proj_w, ffn_w1, ffn_w2);
    ln_kernel<<<NROWS / 8, 256>>>(x, gy, ln1_g, ln1_b);
    k_qkv <<<dim3(12, 1600), 256, smG>>>(qkv_b);
    attn_kernel<<<NSEQ, 256, smQ>>>(lscale);
    k_proj<<<dim3(4, 1600), 256, smG>>>(x, proj_b);
    ln_kernel<<<NROWS / 8, 256>>>(gxf, gy2, ln2_g, ln2_b);
    k_ffn1<<<dim3(16, 1600), 256, smG>>>(ffn_b1);
    k_ffn2<<<dim3(4, 1600), 256, smG>>>(ffn_b2, out);
}

// round 11
// speedup vs baseline: 1.9058x; 1.0912x over previous
#include <cuda_runtime.h>
#include <cuda_bf16.h>
#include <math.h>
#include <stdint.h>

#define NSEQ  8192
#define VTOK  25
#define NROWS 204800          // NSEQ * VTOK
#define DM    256
#define NH    8
#define HD    32
#define DF    1024
#define N3    768
#define LDH   264             // smem A-tile row stride (halves), conflict-free ldmatrix
#define LDT   40              // attn per-head tile row stride (halves)

// packed bf16 fragment weights (uint32 words): [tile][kb32][lane][uint4]
#define BQ_OFF 0
#define BP_OFF 98304
#define B1_OFF 131072
#define B2_OFF 262144
#define WU32   393216

__device__ uint32_t       g_wb[WU32];
__device__ __nv_bfloat16  g_y  [(size_t)NROWS * DM];    // LN1 out
__device__ float          g_qkv[(size_t)NROWS * N3];    // qkv (fp32)
__device__ __nv_bfloat16  g_att[(size_t)NROWS * DM];    // attention out
__device__ float          g_xf [(size_t)NROWS * DM];    // residual after proj (fp32)
__device__ __nv_bfloat16  g_y2 [(size_t)NROWS * DM];    // LN2 out
__device__ __nv_bfloat16  g_h  [(size_t)NROWS * DF];    // FFN hidden

__device__ __forceinline__ float gelu_exact(float v) {
    return 0.5f * v * (1.f + erff(v * 0.70710678118654752440f));
}
__device__ __forceinline__ uint32_t pack_bf2(float lo, float hi) {
    __nv_bfloat162 p;
    p.x = __float2bfloat16_rn(lo);
    p.y = __float2bfloat16_rn(hi);
    return *(uint32_t*)&p;
}

// ---- weight packing to bf16 m16n8k16 B-fragments ----
__global__ void prep_pack(const float* __restrict__ qkv_w, const float* __restrict__ proj_w,
                          const float* __restrict__ f1,    const float* __restrict__ f2) {
    int i = blockIdx.x * 256 + threadIdx.x;
    if (i >= WU32) return;
    int comp = i & 3, lane = (i >> 2) & 31;
    int g = lane >> 2, t4 = lane & 3;
    int klo = 2 * t4 + ((comp & 1) << 3) + ((comp >> 1) << 4);
    const float* W; int ldw, k, col;
    if (i < BP_OFF) {                         // QKV: 96 tiles x 8 kb
        int r2 = i >> 7;  int kb = r2 & 7, tile = r2 >> 3;
        col = tile * 8 + g; k = kb * 32 + klo; W = qkv_w; ldw = N3;
    } else if (i < B1_OFF) {                  // proj: 32 tiles x 8 kb
        int r2 = (i - BP_OFF) >> 7;  int kb = r2 & 7, tile = r2 >> 3;
        col = tile * 8 + g; k = kb * 32 + klo; W = proj_w; ldw = DM;
    } else if (i < B2_OFF) {                  // ffn1: 128 tiles x 8 kb
        int r2 = (i - B1_OFF) >> 7;  int kb = r2 & 7, tile = r2 >> 3;
        col = tile * 8 + g; k = kb * 32 + klo; W = f1; ldw = DF;
    } else {                                  // ffn2: 32 tiles x 32 kb (K=1024)
        int r2 = (i - B2_OFF) >> 7;  int kb = r2 & 31, tile = r2 >> 5;
        col = tile * 8 + g; k = kb * 32 + klo; W = f2; ldw = DM;
    }
    g_wb[i] = pack_bf2(W[(size_t)k * ldw + col], W[(size_t)(k + 1) * ldw + col]);
}

#define MMA_BF(D, A, B0, B1)                                                \
    asm("mma.sync.aligned.m16n8k16.row.col.f32.bf16.bf16.f32 "              \
        "{%0,%1,%2,%3}, {%4,%5,%6,%7}, {%8,%9}, {%0,%1,%2,%3};"             \
        : "+f"(D[0]), "+f"(D[1]), "+f"(D[2]), "+f"(D[3])                    \
        : "r"(A[0]), "r"(A[1]), "r"(A[2]), "r"(A[3]), "r"(B0), "r"(B1))

#define MMA_BF2(D, A0, A1, A2, A3, B0, B1)                                  \
    asm("mma.sync.aligned.m16n8k16.row.col.f32.bf16.bf16.f32 "              \
        "{%0,%1,%2,%3}, {%4,%5,%6,%7}, {%8,%9}, {%0,%1,%2,%3};"             \
        : "+f"(D[0]), "+f"(D[1]), "+f"(D[2]), "+f"(D[3])                    \
        : "r"(A0), "r"(A1), "r"(A2), "r"(A3), "r"(B0), "r"(B1))

#define LDSM4(A, addr)                                                      \
    asm volatile("ldmatrix.sync.aligned.m8n8.x4.shared.b16 {%0,%1,%2,%3}, [%4];" \
        : "=r"(A[0]), "=r"(A[1]), "=r"(A[2]), "=r"(A[3]) : "r"(addr))

#define LDSM4T(A, addr)                                                     \
    asm volatile("ldmatrix.sync.aligned.m8n8.x4.trans.shared.b16 {%0,%1,%2,%3}, [%4];" \
        : "=r"(A[0]), "=r"(A[1]), "=r"(A[2]), "=r"(A[3]) : "r"(addr))

#define LDS128U(r0, r1, r2, r3, addr)                                       \
    asm volatile("ld.shared.v4.u32 {%0,%1,%2,%3}, [%4];"                    \
        : "=r"(r0), "=r"(r1), "=r"(r2), "=r"(r3) : "r"(addr))

__device__ __forceinline__ void cp_async16(uint32_t saddr, const void* g) {
    asm volatile("cp.async.cg.shared.global [%0], [%1], 16;" :: "r"(saddr), "l"(g) : "memory");
}
#define CP_COMMIT() asm volatile("cp.async.commit_group;" ::: "memory")
#define CP_WAIT0()  asm volatile("cp.async.wait_group 0;" ::: "memory")

__device__ __forceinline__ uint32_t ldsm_addr(const __nv_bfloat16* base, int ldh, int lane) {
    return (uint32_t)__cvta_generic_to_shared(base + (lane & 15) * ldh + (lane >> 4) * 8);
}

// Warp computes 32 x NT*8 tile; A via ldmatrix, B fragments from smem (LDS.128).
template<int NT, int KB>
__device__ __forceinline__ void gemm_sm(uint32_t a0addr, uint32_t a1addr,
                                        uint32_t sBaddr, int tbase,
                                        float (&acc)[2][NT][4], int lane)
{
    #pragma unroll
    for (int kb = 0; kb < KB; kb++) {
        uint32_t A0[4], A1[4], A2[4], A3[4];
        LDSM4(A0, a0addr + kb * 64);
        LDSM4(A1, a1addr + kb * 64);
        LDSM4(A2, a0addr + kb * 64 + 32);
        LDSM4(A3, a1addr + kb * 64 + 32);
        #pragma unroll
        for (int nt = 0; nt < NT; nt++) {
            uint32_t b0, b1, b2, b3;
            LDS128U(b0, b1, b2, b3, sBaddr + (((tbase + nt) * KB + kb) * 32 + lane) * 16);
            MMA_BF(acc[0][nt], A0, b0, b1);
            MMA_BF(acc[1][nt], A1, b0, b1);
            MMA_BF(acc[0][nt], A2, b2, b3);
            MMA_BF(acc[1][nt], A3, b2, b3);
        }
    }
}

// ---- LayerNorm: fp32 rows -> bf16 rows ----
__device__ __forceinline__ void ln_row_bf(const float* __restrict__ src,
                                          __nv_bfloat16* __restrict__ dst,
                                          const float* __restrict__ gg,
                                          const float* __restrict__ bb, int lane)
{
    float v[8], s = 0.f, s2 = 0.f;
    #pragma unroll
    for (int j = 0; j < 8; j++) { v[j] = src[lane + 32 * j]; s += v[j]; s2 += v[j] * v[j]; }
    #pragma unroll
    for (int o = 16; o > 0; o >>= 1) {
        s  += __shfl_xor_sync(0xffffffffu, s,  o);
        s2 += __shfl_xor_sync(0xffffffffu, s2, o);
    }
    float mean = s * (1.f / DM);
    float var  = s2 * (1.f / DM) - mean * mean;
    float inv  = rsqrtf(var + 1e-5f);
    #pragma unroll
    for (int j = 0; j < 8; j++) {
        int c = lane + 32 * j;
        dst[c] = __float2bfloat16_rn((v[j] - mean) * inv * gg[c] + bb[c]);
    }
}

__global__ __launch_bounds__(256) void ln_kernel(const float* __restrict__ src,
                                                 __nv_bfloat16* __restrict__ dst,
                                                 const float* __restrict__ gg,
                                                 const float* __restrict__ bb)
{
    int row  = blockIdx.x * 8 + (threadIdx.x >> 5);
    int lane = threadIdx.x & 31;
    ln_row_bf(src + (size_t)row * DM, dst + (size_t)row * DM, gg, bb, lane);
}

// ---- A-tile async loader ----
__device__ __forceinline__ void load_atile_async(const __nv_bfloat16* __restrict__ Ag,
                                                 size_t row0, int srow, int c0,
                                                 __nv_bfloat16* __restrict__ sA, int tid)
{
    uint32_t sbase = (uint32_t)__cvta_generic_to_shared(sA);
    #pragma unroll
    for (int i = 0; i < 16; i++) {
        int idx = tid + i * 256;
        int row = idx >> 5, c8 = idx & 31;
        cp_async16(sbase + (row * LDH + c8 * 8) * 2,
                   Ag + (row0 + row) * (size_t)srow + c0 + c8 * 8);
    }
}

__device__ __forceinline__ void load_btile_async(const uint4* __restrict__ Bg_chunkbase,
                                                 int tile_stride_u4,
                                                 uint32_t sBaddr, int tid)
{
    #pragma unroll
    for (int t = 0; t < 8; t++) {
        cp_async16(sBaddr + (t * 256 + tid) * 16,
                   Bg_chunkbase + (size_t)t * tile_stride_u4 + tid);
    }
}

#define SM_A_BYTES 67584
#define SM_B_BYTES 32768

#define GEMM_PRO()                                                          \
    extern __shared__ __nv_bfloat16 sA[];                                   \
    uint32_t sBaddr = (uint32_t)__cvta_generic_to_shared(sA) + SM_A_BYTES;  \
    const int tid = threadIdx.x, lane = tid & 31;                           \
    const int wid = tid >> 5, wm = wid >> 1, wn = wid & 1;                  \
    const int g = lane >> 2, t4 = lane & 3;                                 \
    const int ntblk = blockIdx.x;                                           \
    const size_t mb = (size_t)blockIdx.y * 128;                             \
    float acc[2][4][4];                                                     \
    _Pragma("unroll") for (int mt = 0; mt < 2; mt++)                        \
    _Pragma("unroll") for (int nt = 0; nt < 4; nt++)                        \
    _Pragma("unroll") for (int e = 0; e < 4; e++) acc[mt][nt][e] = 0.f;

// ---- QKV GEMM -> g_qkv (fp32). grid (12, 1600) ----
__global__ __launch_bounds__(256, 2) void k_qkv(const float* __restrict__ bias)
{
    GEMM_PRO();
    load_atile_async(g_y, mb, DM, 0, sA, tid);
    load_btile_async((const uint4*)g_wb + BQ_OFF / 4 + (size_t)ntblk * 2048, 256, sBaddr, tid);
    CP_COMMIT(); CP_WAIT0();
    __syncthreads();
    uint32_t a0 = ldsm_addr(sA + (wm * 32) * LDH, LDH, lane), a1 = a0 + 16 * LDH * 2;
    gemm_sm<4, 8>(a0, a1, sBaddr, wn * 4, acc, lane);
    const int cb = ntblk * 64 + wn * 32;
    #pragma unroll
    for (int mt = 0; mt < 2; mt++)
        #pragma unroll
        for (int nt = 0; nt < 4; nt++) {
            int c = cb + nt * 8 + 2 * t4;
            float b0 = bias[c], b1 = bias[c + 1];
            #pragma unroll
            for (int hrow = 0; hrow < 2; hrow++) {
                size_t R = mb + wm * 32 + mt * 16 + g + hrow * 8;
                float2 o;
                o.x = acc[mt][nt][2 * hrow]     + b0;
                o.y = acc[mt][nt][2 * hrow + 1] + b1;
                *(float2*)(g_qkv + R * N3 + c) = o;
            }
        }
}

// ---- attention staging helpers ----
__device__ __forceinline__ float row_load_n2(const float* __restrict__ src, float4 (&f)[8]) {
    float n2 = 0.f;
    #pragma unroll
    for (int p = 0; p < 8; p++) {
        f[p] = ((const float4*)src)[p];
        n2 = fmaf(f[p].x, f[p].x, n2);
        n2 = fmaf(f[p].y, f[p].y, n2);
        n2 = fmaf(f[p].z, f[p].z, n2);
        n2 = fmaf(f[p].w, f[p].w, n2);
    }
    return n2;
}
__device__ __forceinline__ void row_store_bf(__nv_bfloat16* __restrict__ dst,
                                             const float4 (&f)[8], float s) {
    #pragma unroll
    for (int q = 0; q < 4; q++) {
        uint4 u;
        u.x = pack_bf2(f[2*q].x * s,   f[2*q].y * s);
        u.y = pack_bf2(f[2*q].z * s,   f[2*q].w * s);
        u.z = pack_bf2(f[2*q+1].x * s, f[2*q+1].y * s);
        u.w = pack_bf2(f[2*q+1].z * s, f[2*q+1].w * s);
        ((uint4*)dst)[q] = u;
    }
}
__device__ __forceinline__ void row_zero(__nv_bfloat16* __restrict__ dst) {
    uint4 z = make_uint4(0, 0, 0, 0);
    #pragma unroll
    for (int q = 0; q < 4; q++) ((uint4*)dst)[q] = z;
}

// ---- attention: block = sequence, warp = head; MMA-based ----
__global__ __launch_bounds__(256, 2) void attn_kernel(const float* __restrict__ logit_scale)
{
    extern __shared__ __nv_bfloat16 smt[];
    const int tid = threadIdx.x, lane = tid & 31, h = tid >> 5;
    const int g = lane >> 2, t4 = lane & 3;
    const size_t seq = blockIdx.x;

    __nv_bfloat16* sq = smt + h * (96 * LDT);
    __nv_bfloat16* sk = sq + 32 * LDT;
    __nv_bfloat16* sv = sk + 32 * LDT;

    const float sc = expf(fminf(logit_scale[h], 4.6051701859880913680f));

    // stage per-head 32x32 bf16 tiles; lane = token row (>=VTOK -> zeros)
    const int i = lane;
    if (i < VTOK) {
        const float* base = g_qkv + ((size_t)seq * VTOK + i) * N3 + h * HD;
        float4 f[8];
        float n2 = row_load_n2(base, f);
        row_store_bf(sq + i * LDT, f,
                     sc * 0.17677669529663688110f / fmaxf(sqrtf(n2), 1e-12f));
        n2 = row_load_n2(base + 256, f);
        row_store_bf(sk + i * LDT, f, 1.f / fmaxf(sqrtf(n2), 1e-12f));
        row_load_n2(base + 512, f);
        row_store_bf(sv + i * LDT, f, 1.f);
    } else {
        row_zero(sq + i * LDT);
        row_zero(sk + i * LDT);
        row_zero(sv + i * LDT);
    }
    __syncwarp();

    // ---- fragments ----
    uint32_t qb = (uint32_t)__cvta_generic_to_shared(sq);
    uint32_t kbb = (uint32_t)__cvta_generic_to_shared(sk);
    uint32_t vbb = (uint32_t)__cvta_generic_to_shared(sv);

    uint32_t aq[2][2][4];          // [m-tile][k-chunk]
    #pragma unroll
    for (int mt = 0; mt < 2; mt++)
        #pragma unroll
        for (int c = 0; c < 2; c++) {
            uint32_t addr = qb + (mt * 16 + (lane & 15)) * (LDT * 2) + (lane >> 4) * 16 + c * 32;
            LDSM4(aq[mt][c], addr);
        }
    uint32_t bk[4][4];             // [n-tile]: {b0c0,b1c0,b0c1,b1c1}
    #pragma unroll
    for (int nt = 0; nt < 4; nt++) {
        uint32_t addr = kbb + (nt * 8 + (lane & 7)) * (LDT * 2) + (lane >> 3) * 16;
        LDSM4(bk[nt], addr);
    }

    // ---- QK^T: logits (already scaled) ----
    float accl[2][4][4];
    #pragma unroll
    for (int mt = 0; mt < 2; mt++)
        #pragma unroll
        for (int nt = 0; nt < 4; nt++)
            #pragma unroll
            for (int e = 0; e < 4; e++) accl[mt][nt][e] = 0.f;
    #pragma unroll
    for (int mt = 0; mt < 2; mt++)
        #pragma unroll
        for (int nt = 0; nt < 4; nt++) {
            MMA_BF(accl[mt][nt], aq[mt][0], bk[nt][0], bk[nt][1]);
            MMA_BF(accl[mt][nt], aq[mt][1], bk[nt][2], bk[nt][3]);
        }

    // ---- softmax over cols (mask c >= VTOK), per row-half, quad reduce ----
    #pragma unroll
    for (int mt = 0; mt < 2; mt++)
        #pragma unroll
        for (int hrow = 0; hrow < 2; hrow++) {
            float m = -1e30f;
            #pragma unroll
            for (int nt = 0; nt < 4; nt++)
                #pragma unroll
                for (int e = 0; e < 2; e++) {
                    int c = nt * 8 + 2 * t4 + e;
                    float vl = (c < VTOK) ? accl[mt][nt][2 * hrow + e] : -1e30f;
                    accl[mt][nt][2 * hrow + e] = vl;
                    m = fmaxf(m, vl);
                }
            m = fmaxf(m, __shfl_xor_sync(0xffffffffu, m, 1));
            m = fmaxf(m, __shfl_xor_sync(0xffffffffu, m, 2));
            float s = 0.f;
            #pragma unroll
            for (int nt = 0; nt < 4; nt++)
                #pragma unroll
                for (int e = 0; e < 2; e++) {
                    float p = __expf(accl[mt][nt][2 * hrow + e] - m);
                    accl[mt][nt][2 * hrow + e] = p;
                    s += p;
                }
            s += __shfl_xor_sync(0xffffffffu, s, 1);
            s += __shfl_xor_sync(0xffffffffu, s, 2);
            float rs = 1.f / s;
            #pragma unroll
            for (int nt = 0; nt < 4; nt++)
                #pragma unroll
                for (int e = 0; e < 2; e++) accl[mt][nt][2 * hrow + e] *= rs;
        }

    // ---- P: C-frags -> A-frags (in-register; col-pair == k-pair layout) ----
    uint32_t pa[2][2][4];
    #pragma unroll
    for (int mt = 0; mt < 2; mt++)
        #pragma unroll
        for (int c = 0; c < 2; c++) {
            pa[mt][c][0] = pack_bf2(accl[mt][2*c  ][0], accl[mt][2*c  ][1]);
            pa[mt][c][1] = pack_bf2(accl[mt][2*c  ][2], accl[mt][2*c  ][3]);
            pa[mt][c][2] = pack_bf2(accl[mt][2*c+1][0], accl[mt][2*c+1][1]);
            pa[mt][c][3] = pack_bf2(accl[mt][2*c+1][2], accl[mt][2*c+1][3]);
        }

    // ---- V B-frags via ldmatrix.trans: [k-chunk][n-pair] ----
    uint32_t bv[2][2][4];
    #pragma unroll
    for (int c = 0; c < 2; c++)
        #pragma unroll
        for (int np = 0; np < 2; np++) {
            uint32_t addr = vbb + (c * 16 + ((lane >> 3) & 1) * 8 + (lane & 7)) * (LDT * 2)
                          + np * 32 + (lane >> 4) * 16;
            LDSM4T(bv[c][np], addr);
        }

    // ---- O = P @ V ----
    float acco[2][4][4];
    #pragma unroll
    for (int mt = 0; mt < 2; mt++)
        #pragma unroll
        for (int nt = 0; nt < 4; nt++)
            #pragma unroll
            for (int e = 0; e < 4; e++) acco[mt][nt][e] = 0.f;
    #pragma unroll
    for (int mt = 0; mt < 2; mt++)
        #pragma unroll
        for (int nt = 0; nt < 4; nt++) {
            int np = nt >> 1, hi = (nt & 1) * 2;
            MMA_BF(acco[mt][nt], pa[mt][0], bv[0][np][hi], bv[0][np][hi + 1]);
            MMA_BF(acco[mt][nt], pa[mt][1], bv[1][np][hi], bv[1][np][hi + 1]);
        }

    // ---- store to g_att (bf16) ----
    #pragma unroll
    for (int mt = 0; mt < 2; mt++)
        #pragma unroll
        for (int hrow = 0; hrow < 2; hrow++) {
            int token = mt * 16 + g + hrow * 8;
            if (token < VTOK) {
                __nv_bfloat16* og = g_att + (seq * VTOK + token) * DM + h * HD;
                #pragma unroll
                for (int nt = 0; nt < 4; nt++)
                    *(uint32_t*)(og + nt * 8 + 2 * t4) =
                        pack_bf2(acco[mt][nt][2 * hrow], acco[mt][nt][2 * hrow + 1]);
            }
        }
}

// ---- proj GEMM + residual -> g_xf (fp32). grid (4, 1600) ----
__global__ __launch_bounds__(256, 2) void k_proj(const float* __restrict__ x,
                                                 const float* __restrict__ bias)
{
    GEMM_PRO();
    load_atile_async(g_att, mb, DM, 0, sA, tid);
    load_btile_async((const uint4*)g_wb + BP_OFF / 4 + (size_t)ntblk * 2048, 256, sBaddr, tid);
    CP_COMMIT(); CP_WAIT0();
    __syncthreads();
    uint32_t a0 = ldsm_addr(sA + (wm * 32) * LDH, LDH, lane), a1 = a0 + 16 * LDH * 2;
    gemm_sm<4, 8>(a0, a1, sBaddr, wn * 4, acc, lane);
    const int cb = ntblk * 64 + wn * 32;
    #pragma unroll
    for (int mt = 0; mt < 2; mt++)
        #pragma unroll
        for (int nt = 0; nt < 4; nt++) {
            int c = cb + nt * 8 + 2 * t4;
            float b0 = bias[c], b1 = bias[c + 1];
            #pragma unroll
            for (int hrow = 0; hrow < 2; hrow++) {
                size_t R = mb + wm * 32 + mt * 16 + g + hrow * 8;
                float2 xv = *(const float2*)(x + R * DM + c);
                float2 o;
                o.x = xv.x + acc[mt][nt][2 * hrow]     + b0;
                o.y = xv.y + acc[mt][nt][2 * hrow + 1] + b1;
                *(float2*)(g_xf + R * DM + c) = o;
            }
        }
}

// ---- FFN1 GEMM + gelu -> g_h (bf16). grid (16, 1600) ----
__global__ __launch_bounds__(256, 2) void k_ffn1(const float* __restrict__ bias)
{
    GEMM_PRO();
    load_atile_async(g_y2, mb, DM, 0, sA, tid);
    load_btile_async((const uint4*)g_wb + B1_OFF / 4 + (size_t)ntblk * 2048, 256, sBaddr, tid);
    CP_COMMIT(); CP_WAIT0();
    __syncthreads();
    uint32_t a0 = ldsm_addr(sA + (wm * 32) * LDH, LDH, lane), a1 = a0 + 16 * LDH * 2;
    gemm_sm<4, 8>(a0, a1, sBaddr, wn * 4, acc, lane);
    const int cb = ntblk * 64 + wn * 32;
    #pragma unroll
    for (int mt = 0; mt < 2; mt++)
        #pragma unroll
        for (int nt = 0; nt < 4; nt++) {
            int c = cb + nt * 8 + 2 * t4;
            float b0 = bias[c], b1 = bias[c + 1];
            #pragma unroll
            for (int hrow = 0; hrow < 2; hrow++) {
                size_t R = mb + wm * 32 + mt * 16 + g + hrow * 8;
                *(uint32_t*)(g_h + R * DF + c) =
                    pack_bf2(gelu_exact(acc[mt][nt][2 * hrow] + b0),
                             gelu_exact(acc[mt][nt][2 * hrow + 1] + b1));
            }
        }
}

// ---- FFN2 GEMM + residual -> out (fp32). grid (4, 1600) ----
__global__ __launch_bounds__(256, 2) void k_ffn2(const float* __restrict__ bias,
                                                 float* __restrict__ out)
{
    GEMM_PRO();
    uint32_t a0 = ldsm_addr(sA + (wm * 32) * LDH, LDH, lane), a1 = a0 + 16 * LDH * 2;
    #pragma unroll
    for (int ch = 0; ch < 4; ch++) {
        if (ch) __syncthreads();
        load_atile_async(g_h, mb, DF, ch * 256, sA, tid);
        {
            const uint4* bsrc = (const uint4*)g_wb + B2_OFF / 4
                              + (size_t)ntblk * 8 * 1024 + ch * 256;
            load_btile_async(bsrc, 1024, sBaddr, tid);
        }
        CP_COMMIT(); CP_WAIT0();
        __syncthreads();
        gemm_sm<4, 8>(a0, a1, sBaddr, wn * 4, acc, lane);
    }
    const int cb = ntblk * 64 + wn * 32;
    #pragma unroll
    for (int mt = 0; mt < 2; mt++)
        #pragma unroll
        for (int nt = 0; nt < 4; nt++) {
            int c = cb + nt * 8 + 2 * t4;
            float b0 = bias[c], b1 = bias[c + 1];
            #pragma unroll
            for (int hrow = 0; hrow < 2; hrow++) {
                size_t R = mb + wm * 32 + mt * 16 + g + hrow * 8;
                float2 xv = *(const float2*)(g_xf + R * DM + c);
                float2 o;
                o.x = xv.x + acc[mt][nt][2 * hrow]     + b0;
                o.y = xv.y + acc[mt][nt][2 * hrow + 1] + b1;
                *(float2*)(out + R * DM + c) = o;
            }
        }
}

extern "C" void kernel_launch(void* const* d_in, const int* in_sizes, int n_in,
                              void* d_out, int out_size)
{
    const float* x      = (const float*)d_in[0];
    const float* ln1_g  = (const float*)d_in[1];
    const float* ln1_b  = (const float*)d_in[2];
    const float* qkv_w  = (const float*)d_in[3];
    const float* qkv_b  = (const float*)d_in[4];
    const float* proj_w = (const float*)d_in[5];
    const float* proj_b = (const float*)d_in[6];
    const float* lscale = (const float*)d_in[7];
    const float* ln2_g  = (const float*)d_in[8];
    const float* ln2_b  = (const float*)d_in[9];
    const float* ffn_w1 = (const float*)d_in[10];
    const float* ffn_b1 = (const float*)d_in[11];
    const float* ffn_w2 = (const float*)d_in[12];
    const float* ffn_b2 = (const float*)d_in[13];
    float* out = (float*)d_out;

    __nv_bfloat16 *gy, *gy2;
    cudaGetSymbolAddress((void**)&gy,  g_y);
    cudaGetSymbolAddress((void**)&gy2, g_y2);
    float* gxf;
    cudaGetSymbolAddress((void**)&gxf, g_xf);

    const int smG = SM_A_BYTES + SM_B_BYTES;        // 100352
    const int smQ = 8 * 96 * LDT * 2;               // 61440 (attn tiles)
    cudaFuncSetAttribute(k_qkv,  cudaFuncAttributeMaxDynamicSharedMemorySize, smG);
    cudaFuncSetAttribute(k_proj, cudaFuncAttributeMaxDynamicSharedMemorySize, smG);
    cudaFuncSetAttribute(k_ffn1, cudaFuncAttributeMaxDynamicSharedMemorySize, smG);
    cudaFuncSetAttribute(k_ffn2, cudaFuncAttributeMaxDynamicSharedMemorySize, smG);
    cudaFuncSetAttribute(attn_kernel, cudaFuncAttributeMaxDynamicSharedMemorySize, smQ);

    prep_pack<<<(WU32 + 255) / 256, 256>>>(qkv_w, proj_w, ffn_w1, ffn_w2);
    ln_kernel<<<NROWS / 8, 256>>>(x, gy, ln1_g, ln1_b);
    k_qkv <<<dim3(12, 1600), 256, smG>>>(qkv_b);
    attn_kernel<<<NSEQ, 256, smQ>>>(lscale);
    k_proj<<<dim3(4, 1600), 256, smG>>>(x, proj_b);
    ln_kernel<<<NROWS / 8, 256>>>(gxf, gy2, ln2_g, ln2_b);
    k_ffn1<<<dim3(16, 1600), 256, smG>>>(ffn_b1);
    k_ffn2<<<dim3(4, 1600), 256, smG>>>(ffn_b2, out);
}

// round 12
// speedup vs baseline: 2.0163x; 1.0580x over previous
#include <cuda_runtime.h>
#include <cuda_bf16.h>
#include <math.h>
#include <stdint.h>

#define NSEQ  8192
#define VTOK  25
#define NROWS 204800          // NSEQ * VTOK
#define DM    256
#define NH    8
#define HD    32
#define DF    1024
#define N3    768
#define LDH   264             // smem A-tile row stride (halves), conflict-free ldmatrix
#define LDT   40              // attn per-head tile row stride (halves)
#define HSTR  3848            // attn per-head smem stride (96*LDT + 8: bank-spread pad)

// packed bf16 fragment weights (uint32 words): [tile][kb32][lane][uint4]
#define BQ_OFF 0
#define BP_OFF 98304
#define B1_OFF 131072
#define B2_OFF 262144
#define WU32   393216

__device__ uint32_t       g_wb[WU32];
__device__ __nv_bfloat16  g_y  [(size_t)NROWS * DM];    // LN1 out
__device__ __nv_bfloat16  g_qkvh[(size_t)NROWS * N3];   // q-hat / k-hat / v (bf16)
__device__ __nv_bfloat16  g_att[(size_t)NROWS * DM];    // attention out
__device__ float          g_xf [(size_t)NROWS * DM];    // residual after proj (fp32)
__device__ __nv_bfloat16  g_y2 [(size_t)NROWS * DM];    // LN2 out
__device__ __nv_bfloat16  g_h  [(size_t)NROWS * DF];    // FFN hidden

__device__ __forceinline__ float gelu_exact(float v) {
    return 0.5f * v * (1.f + erff(v * 0.70710678118654752440f));
}
__device__ __forceinline__ uint32_t pack_bf2(float lo, float hi) {
    __nv_bfloat162 p;
    p.x = __float2bfloat16_rn(lo);
    p.y = __float2bfloat16_rn(hi);
    return *(uint32_t*)&p;
}

// ---- weight packing to bf16 m16n8k16 B-fragments ----
__global__ void prep_pack(const float* __restrict__ qkv_w, const float* __restrict__ proj_w,
                          const float* __restrict__ f1,    const float* __restrict__ f2) {
    int i = blockIdx.x * 256 + threadIdx.x;
    if (i >= WU32) return;
    int comp = i & 3, lane = (i >> 2) & 31;
    int g = lane >> 2, t4 = lane & 3;
    int klo = 2 * t4 + ((comp & 1) << 3) + ((comp >> 1) << 4);
    const float* W; int ldw, k, col;
    if (i < BP_OFF) {                         // QKV: 96 tiles x 8 kb
        int r2 = i >> 7;  int kb = r2 & 7, tile = r2 >> 3;
        col = tile * 8 + g; k = kb * 32 + klo; W = qkv_w; ldw = N3;
    } else if (i < B1_OFF) {                  // proj: 32 tiles x 8 kb
        int r2 = (i - BP_OFF) >> 7;  int kb = r2 & 7, tile = r2 >> 3;
        col = tile * 8 + g; k = kb * 32 + klo; W = proj_w; ldw = DM;
    } else if (i < B2_OFF) {                  // ffn1: 128 tiles x 8 kb
        int r2 = (i - B1_OFF) >> 7;  int kb = r2 & 7, tile = r2 >> 3;
        col = tile * 8 + g; k = kb * 32 + klo; W = f1; ldw = DF;
    } else {                                  // ffn2: 32 tiles x 32 kb (K=1024)
        int r2 = (i - B2_OFF) >> 7;  int kb = r2 & 31, tile = r2 >> 5;
        col = tile * 8 + g; k = kb * 32 + klo; W = f2; ldw = DM;
    }
    g_wb[i] = pack_bf2(W[(size_t)k * ldw + col], W[(size_t)(k + 1) * ldw + col]);
}

#define MMA_BF(D, A, B0, B1)                                                \
    asm("mma.sync.aligned.m16n8k16.row.col.f32.bf16.bf16.f32 "              \
        "{%0,%1,%2,%3}, {%4,%5,%6,%7}, {%8,%9}, {%0,%1,%2,%3};"             \
        : "+f"(D[0]), "+f"(D[1]), "+f"(D[2]), "+f"(D[3])                    \
        : "r"(A[0]), "r"(A[1]), "r"(A[2]), "r"(A[3]), "r"(B0), "r"(B1))

#define LDSM4(A, addr)                                                      \
    asm volatile("ldmatrix.sync.aligned.m8n8.x4.shared.b16 {%0,%1,%2,%3}, [%4];" \
        : "=r"(A[0]), "=r"(A[1]), "=r"(A[2]), "=r"(A[3]) : "r"(addr))

#define LDSM4T(A, addr)                                                     \
    asm volatile("ldmatrix.sync.aligned.m8n8.x4.trans.shared.b16 {%0,%1,%2,%3}, [%4];" \
        : "=r"(A[0]), "=r"(A[1]), "=r"(A[2]), "=r"(A[3]) : "r"(addr))

#define LDS128U(r0, r1, r2, r3, addr)                                       \
    asm volatile("ld.shared.v4.u32 {%0,%1,%2,%3}, [%4];"                    \
        : "=r"(r0), "=r"(r1), "=r"(r2), "=r"(r3) : "r"(addr))

__device__ __forceinline__ void cp_async16(uint32_t saddr, const void* g) {
    asm volatile("cp.async.cg.shared.global [%0], [%1], 16;" :: "r"(saddr), "l"(g) : "memory");
}
#define CP_COMMIT() asm volatile("cp.async.commit_group;" ::: "memory")
#define CP_WAIT0()  asm volatile("cp.async.wait_group 0;" ::: "memory")

__device__ __forceinline__ uint32_t ldsm_addr(const __nv_bfloat16* base, int ldh, int lane) {
    return (uint32_t)__cvta_generic_to_shared(base + (lane & 15) * ldh + (lane >> 4) * 8);
}

// Warp computes 32 x NT*8 tile; A via ldmatrix, B fragments from smem (LDS.128).
template<int NT, int KB>
__device__ __forceinline__ void gemm_sm(uint32_t a0addr, uint32_t a1addr,
                                        uint32_t sBaddr, int tbase,
                                        float (&acc)[2][NT][4], int lane)
{
    #pragma unroll
    for (int kb = 0; kb < KB; kb++) {
        uint32_t A0[4], A1[4], A2[4], A3[4];
        LDSM4(A0, a0addr + kb * 64);
        LDSM4(A1, a1addr + kb * 64);
        LDSM4(A2, a0addr + kb * 64 + 32);
        LDSM4(A3, a1addr + kb * 64 + 32);
        #pragma unroll
        for (int nt = 0; nt < NT; nt++) {
            uint32_t b0, b1, b2, b3;
            LDS128U(b0, b1, b2, b3, sBaddr + (((tbase + nt) * KB + kb) * 32 + lane) * 16);
            MMA_BF(acc[0][nt], A0, b0, b1);
            MMA_BF(acc[1][nt], A1, b0, b1);
            MMA_BF(acc[0][nt], A2, b2, b3);
            MMA_BF(acc[1][nt], A3, b2, b3);
        }
    }
}

// ---- LayerNorm: fp32 rows -> bf16 rows ----
__device__ __forceinline__ void ln_row_bf(const float* __restrict__ src,
                                          __nv_bfloat16* __restrict__ dst,
                                          const float* __restrict__ gg,
                                          const float* __restrict__ bb, int lane)
{
    float v[8], s = 0.f, s2 = 0.f;
    #pragma unroll
    for (int j = 0; j < 8; j++) { v[j] = src[lane + 32 * j]; s += v[j]; s2 += v[j] * v[j]; }
    #pragma unroll
    for (int o = 16; o > 0; o >>= 1) {
        s  += __shfl_xor_sync(0xffffffffu, s,  o);
        s2 += __shfl_xor_sync(0xffffffffu, s2, o);
    }
    float mean = s * (1.f / DM);
    float var  = s2 * (1.f / DM) - mean * mean;
    float inv  = rsqrtf(var + 1e-5f);
    #pragma unroll
    for (int j = 0; j < 8; j++) {
        int c = lane + 32 * j;
        dst[c] = __float2bfloat16_rn((v[j] - mean) * inv * gg[c] + bb[c]);
    }
}

__global__ __launch_bounds__(256) void ln_kernel(const float* __restrict__ src,
                                                 __nv_bfloat16* __restrict__ dst,
                                                 const float* __restrict__ gg,
                                                 const float* __restrict__ bb)
{
    int row  = blockIdx.x * 8 + (threadIdx.x >> 5);
    int lane = threadIdx.x & 31;
    ln_row_bf(src + (size_t)row * DM, dst + (size_t)row * DM, gg, bb, lane);
}

// ---- A-tile async loader ----
__device__ __forceinline__ void load_atile_async(const __nv_bfloat16* __restrict__ Ag,
                                                 size_t row0, int srow, int c0,
                                                 __nv_bfloat16* __restrict__ sA, int tid)
{
    uint32_t sbase = (uint32_t)__cvta_generic_to_shared(sA);
    #pragma unroll
    for (int i = 0; i < 16; i++) {
        int idx = tid + i * 256;
        int row = idx >> 5, c8 = idx & 31;
        cp_async16(sbase + (row * LDH + c8 * 8) * 2,
                   Ag + (row0 + row) * (size_t)srow + c0 + c8 * 8);
    }
}

__device__ __forceinline__ void load_btile_async(const uint4* __restrict__ Bg_chunkbase,
                                                 int tile_stride_u4,
                                                 uint32_t sBaddr, int tid)
{
    #pragma unroll
    for (int t = 0; t < 8; t++) {
        cp_async16(sBaddr + (t * 256 + tid) * 16,
                   Bg_chunkbase + (size_t)t * tile_stride_u4 + tid);
    }
}

#define SM_A_BYTES 67584
#define SM_B_BYTES 32768

#define GEMM_PRO()                                                          \
    extern __shared__ __nv_bfloat16 sA[];                                   \
    uint32_t sBaddr = (uint32_t)__cvta_generic_to_shared(sA) + SM_A_BYTES;  \
    const int tid = threadIdx.x, lane = tid & 31;                           \
    const int wid = tid >> 5, wm = wid >> 1, wn = wid & 1;                  \
    const int g = lane >> 2, t4 = lane & 3;                                 \
    const int ntblk = blockIdx.x;                                           \
    const size_t mb = (size_t)blockIdx.y * 128;                             \
    float acc[2][4][4];                                                     \
    _Pragma("unroll") for (int mt = 0; mt < 2; mt++)                        \
    _Pragma("unroll") for (int nt = 0; nt < 4; nt++)                        \
    _Pragma("unroll") for (int e = 0; e < 4; e++) acc[mt][nt][e] = 0.f;

// ---- QKV GEMM + fused q/k L2-normalization -> g_qkvh (bf16). grid (12, 1600) ----
// Warp's 32 cols = one head's span; row norm = quad shfl reduce (fp32-exact).
__global__ __launch_bounds__(256, 2) void k_qkv(const float* __restrict__ bias,
                                                const float* __restrict__ lscale)
{
    GEMM_PRO();
    load_atile_async(g_y, mb, DM, 0, sA, tid);
    load_btile_async((const uint4*)g_wb + BQ_OFF / 4 + (size_t)ntblk * 2048, 256, sBaddr, tid);
    CP_COMMIT(); CP_WAIT0();
    __syncthreads();
    uint32_t a0 = ldsm_addr(sA + (wm * 32) * LDH, LDH, lane), a1 = a0 + 16 * LDH * 2;
    gemm_sm<4, 8>(a0, a1, sBaddr, wn * 4, acc, lane);

    const int cb = ntblk * 64 + wn * 32;
    const bool donorm = (ntblk < 8);
    float qmul = 1.f;
    if (ntblk < 4)
        qmul = expf(fminf(lscale[(cb & 255) >> 5], 4.6051701859880913680f))
             * 0.17677669529663688110f;     // sc_h / sqrt(32)

    float bv[8];
    #pragma unroll
    for (int nt = 0; nt < 4; nt++) {
        bv[2 * nt]     = bias[cb + nt * 8 + 2 * t4];
        bv[2 * nt + 1] = bias[cb + nt * 8 + 2 * t4 + 1];
    }

    #pragma unroll
    for (int mt = 0; mt < 2; mt++)
        #pragma unroll
        for (int hrow = 0; hrow < 2; hrow++) {
            float v[8];
            #pragma unroll
            for (int nt = 0; nt < 4; nt++) {
                v[2 * nt]     = acc[mt][nt][2 * hrow]     + bv[2 * nt];
                v[2 * nt + 1] = acc[mt][nt][2 * hrow + 1] + bv[2 * nt + 1];
            }
            float s = qmul;
            if (donorm) {
                float ssq = 0.f;
                #pragma unroll
                for (int e = 0; e < 8; e++) ssq = fmaf(v[e], v[e], ssq);
                ssq += __shfl_xor_sync(0xffffffffu, ssq, 1);
                ssq += __shfl_xor_sync(0xffffffffu, ssq, 2);
                s = qmul / fmaxf(sqrtf(ssq), 1e-12f);
            }
            size_t R = mb + wm * 32 + mt * 16 + g + hrow * 8;
            #pragma unroll
            for (int nt = 0; nt < 4; nt++)
                *(uint32_t*)(g_qkvh + R * N3 + cb + nt * 8 + 2 * t4) =
                    pack_bf2(v[2 * nt] * s, v[2 * nt + 1] * s);
        }
}

// ---- attention: block = sequence, warp = head; pure MMA (inputs pre-normalized) ----
__global__ __launch_bounds__(256, 2) void attn_kernel()
{
    extern __shared__ __nv_bfloat16 smt[];
    const int tid = threadIdx.x, lane = tid & 31, h = tid >> 5;
    const int g = lane >> 2, t4 = lane & 3;
    const size_t seq = blockIdx.x;

    // coalesced CTA-wide stage: 25 x 768 bf16 -> per-head tiles (2400 uint4)
    const uint4* src = (const uint4*)(g_qkvh + seq * (size_t)(VTOK * N3));
    #pragma unroll
    for (int it = 0; it < 10; it++) {
        int idx = tid + it * 256;
        if (idx < 2400) {
            int row = idx / 96, c8 = idx - row * 96;
            int col = c8 * 8;
            int region = col >> 8;              // 0=q 1=k 2=v
            int head = (col & 255) >> 5;
            *(uint4*)(smt + head * HSTR + region * (32 * LDT) + row * LDT + (col & 31)) = src[idx];
        }
    }
    // zero v rows 25..31 (NaN*0 hazard); q/k garbage rows are masked downstream
    if (tid < 224) {
        int head = tid / 28, i2 = tid % 28;
        uint4 z = make_uint4(0, 0, 0, 0);
        *(uint4*)(smt + head * HSTR + 2 * (32 * LDT) + (25 + (i2 >> 2)) * LDT + (i2 & 3) * 8) = z;
    }
    __syncthreads();

    __nv_bfloat16* sq = smt + h * HSTR;
    __nv_bfloat16* sk = sq + 32 * LDT;
    __nv_bfloat16* sv = sk + 32 * LDT;

    uint32_t qb  = (uint32_t)__cvta_generic_to_shared(sq);
    uint32_t kbb = (uint32_t)__cvta_generic_to_shared(sk);
    uint32_t vbb = (uint32_t)__cvta_generic_to_shared(sv);

    uint32_t aq[2][2][4];          // [m-tile][k-chunk]
    #pragma unroll
    for (int mt = 0; mt < 2; mt++)
        #pragma unroll
        for (int c = 0; c < 2; c++) {
            uint32_t addr = qb + (mt * 16 + (lane & 15)) * (LDT * 2) + (lane >> 4) * 16 + c * 32;
            LDSM4(aq[mt][c], addr);
        }
    uint32_t bk[4][4];             // [n-tile]: {b0c0,b1c0,b0c1,b1c1}
    #pragma unroll
    for (int nt = 0; nt < 4; nt++) {
        uint32_t addr = kbb + (nt * 8 + (lane & 7)) * (LDT * 2) + (lane >> 3) * 16;
        LDSM4(bk[nt], addr);
    }

    // ---- QK^T (logits fully scaled already) ----
    float accl[2][4][4];
    #pragma unroll
    for (int mt = 0; mt < 2; mt++)
        #pragma unroll
        for (int nt = 0; nt < 4; nt++)
            #pragma unroll
            for (int e = 0; e < 4; e++) accl[mt][nt][e] = 0.f;
    #pragma unroll
    for (int mt = 0; mt < 2; mt++)
        #pragma unroll
        for (int nt = 0; nt < 4; nt++) {
            MMA_BF(accl[mt][nt], aq[mt][0], bk[nt][0], bk[nt][1]);
            MMA_BF(accl[mt][nt], aq[mt][1], bk[nt][2], bk[nt][3]);
        }

    // ---- softmax over cols (mask c >= VTOK), per row-half, quad reduce ----
    #pragma unroll
    for (int mt = 0; mt < 2; mt++)
        #pragma unroll
        for (int hrow = 0; hrow < 2; hrow++) {
            float m = -1e30f;
            #pragma unroll
            for (int nt = 0; nt < 4; nt++)
                #pragma unroll
                for (int e = 0; e < 2; e++) {
                    int c = nt * 8 + 2 * t4 + e;
                    float vl = (c < VTOK) ? accl[mt][nt][2 * hrow + e] : -1e30f;
                    accl[mt][nt][2 * hrow + e] = vl;
                    m = fmaxf(m, vl);
                }
            m = fmaxf(m, __shfl_xor_sync(0xffffffffu, m, 1));
            m = fmaxf(m, __shfl_xor_sync(0xffffffffu, m, 2));
            float s = 0.f;
            #pragma unroll
            for (int nt = 0; nt < 4; nt++)
                #pragma unroll
                for (int e = 0; e < 2; e++) {
                    float p = __expf(accl[mt][nt][2 * hrow + e] - m);
                    accl[mt][nt][2 * hrow + e] = p;
                    s += p;
                }
            s += __shfl_xor_sync(0xffffffffu, s, 1);
            s += __shfl_xor_sync(0xffffffffu, s, 2);
            float rs = 1.f / s;
            #pragma unroll
            for (int nt = 0; nt < 4; nt++)
                #pragma unroll
                for (int e = 0; e < 2; e++) accl[mt][nt][2 * hrow + e] *= rs;
        }

    // ---- P: C-frags -> A-frags (in-register) ----
    uint32_t pa[2][2][4];
    #pragma unroll
    for (int mt = 0; mt < 2; mt++)
        #pragma unroll
        for (int c = 0; c < 2; c++) {
            pa[mt][c][0] = pack_bf2(accl[mt][2*c  ][0], accl[mt][2*c  ][1]);
            pa[mt][c][1] = pack_bf2(accl[mt][2*c  ][2], accl[mt][2*c  ][3]);
            pa[mt][c][2] = pack_bf2(accl[mt][2*c+1][0], accl[mt][2*c+1][1]);
            pa[mt][c][3] = pack_bf2(accl[mt][2*c+1][2], accl[mt][2*c+1][3]);
        }

    // ---- V B-frags via ldmatrix.trans ----
    uint32_t bv[2][2][4];
    #pragma unroll
    for (int c = 0; c < 2; c++)
        #pragma unroll
        for (int np = 0; np < 2; np++) {
            uint32_t addr = vbb + (c * 16 + ((lane >> 3) & 1) * 8 + (lane & 7)) * (LDT * 2)
                          + np * 32 + (lane >> 4) * 16;
            LDSM4T(bv[c][np], addr);
        }

    // ---- O = P @ V ----
    float acco[2][4][4];
    #pragma unroll
    for (int mt = 0; mt < 2; mt++)
        #pragma unroll
        for (int nt = 0; nt < 4; nt++)
            #pragma unroll
            for (int e = 0; e < 4; e++) acco[mt][nt][e] = 0.f;
    #pragma unroll
    for (int mt = 0; mt < 2; mt++)
        #pragma unroll
        for (int nt = 0; nt < 4; nt++) {
            int np = nt >> 1, hi = (nt & 1) * 2;
            MMA_BF(acco[mt][nt], pa[mt][0], bv[0][np][hi], bv[0][np][hi + 1]);
            MMA_BF(acco[mt][nt], pa[mt][1], bv[1][np][hi], bv[1][np][hi + 1]);
        }

    // ---- store to g_att (bf16) ----
    #pragma unroll
    for (int mt = 0; mt < 2; mt++)
        #pragma unroll
        for (int hrow = 0; hrow < 2; hrow++) {
            int token = mt * 16 + g + hrow * 8;
            if (token < VTOK) {
                __nv_bfloat16* og = g_att + (seq * VTOK + token) * DM + h * HD;
                #pragma unroll
                for (int nt = 0; nt < 4; nt++)
                    *(uint32_t*)(og + nt * 8 + 2 * t4) =
                        pack_bf2(acco[mt][nt][2 * hrow], acco[mt][nt][2 * hrow + 1]);
            }
        }
}

// ---- proj GEMM + residual -> g_xf (fp32). grid (4, 1600) ----
__global__ __launch_bounds__(256, 2) void k_proj(const float* __restrict__ x,
                                                 const float* __restrict__ bias)
{
    GEMM_PRO();
    load_atile_async(g_att, mb, DM, 0, sA, tid);
    load_btile_async((const uint4*)g_wb + BP_OFF / 4 + (size_t)ntblk * 2048, 256, sBaddr, tid);
    CP_COMMIT(); CP_WAIT0();
    __syncthreads();
    uint32_t a0 = ldsm_addr(sA + (wm * 32) * LDH, LDH, lane), a1 = a0 + 16 * LDH * 2;
    gemm_sm<4, 8>(a0, a1, sBaddr, wn * 4, acc, lane);
    const int cb = ntblk * 64 + wn * 32;
    #pragma unroll
    for (int mt = 0; mt < 2; mt++)
        #pragma unroll
        for (int nt = 0; nt < 4; nt++) {
            int c = cb + nt * 8 + 2 * t4;
            float b0 = bias[c], b1 = bias[c + 1];
            #pragma unroll
            for (int hrow = 0; hrow < 2; hrow++) {
                size_t R = mb + wm * 32 + mt * 16 + g + hrow * 8;
                float2 xv = *(const float2*)(x + R * DM + c);
                float2 o;
                o.x = xv.x + acc[mt][nt][2 * hrow]     + b0;
                o.y = xv.y + acc[mt][nt][2 * hrow + 1] + b1;
                *(float2*)(g_xf + R * DM + c) = o;
            }
        }
}

// ---- FFN1 GEMM + gelu -> g_h (bf16). grid (16, 1600) ----
__global__ __launch_bounds__(256, 2) void k_ffn1(const float* __restrict__ bias)
{
    GEMM_PRO();
    load_atile_async(g_y2, mb, DM, 0, sA, tid);
    load_btile_async((const uint4*)g_wb + B1_OFF / 4 + (size_t)ntblk * 2048, 256, sBaddr, tid);
    CP_COMMIT(); CP_WAIT0();
    __syncthreads();
    uint32_t a0 = ldsm_addr(sA + (wm * 32) * LDH, LDH, lane), a1 = a0 + 16 * LDH * 2;
    gemm_sm<4, 8>(a0, a1, sBaddr, wn * 4, acc, lane);
    const int cb = ntblk * 64 + wn * 32;
    #pragma unroll
    for (int mt = 0; mt < 2; mt++)
        #pragma unroll
        for (int nt = 0; nt < 4; nt++) {
            int c = cb + nt * 8 + 2 * t4;
            float b0 = bias[c], b1 = bias[c + 1];
            #pragma unroll
            for (int hrow = 0; hrow < 2; hrow++) {
                size_t R = mb + wm * 32 + mt * 16 + g + hrow * 8;
                *(uint32_t*)(g_h + R * DF + c) =
                    pack_bf2(gelu_exact(acc[mt][nt][2 * hrow] + b0),
                             gelu_exact(acc[mt][nt][2 * hrow + 1] + b1));
            }
        }
}

// ---- FFN2 GEMM + residual -> out (fp32). grid (4, 1600) ----
__global__ __launch_bounds__(256, 2) void k_ffn2(const float* __restrict__ bias,
                                                 float* __restrict__ out)
{
    GEMM_PRO();
    uint32_t a0 = ldsm_addr(sA + (wm * 32) * LDH, LDH, lane), a1 = a0 + 16 * LDH * 2;
    #pragma unroll
    for (int ch = 0; ch < 4; ch++) {
        if (ch) __syncthreads();
        load_atile_async(g_h, mb, DF, ch * 256, sA, tid);
        {
            const uint4* bsrc = (const uint4*)g_wb + B2_OFF / 4
                              + (size_t)ntblk * 8 * 1024 + ch * 256;
            load_btile_async(bsrc, 1024, sBaddr, tid);
        }
        CP_COMMIT(); CP_WAIT0();
        __syncthreads();
        gemm_sm<4, 8>(a0, a1, sBaddr, wn * 4, acc, lane);
    }
    const int cb = ntblk * 64 + wn * 32;
    #pragma unroll
    for (int mt = 0; mt < 2; mt++)
        #pragma unroll
        for (int nt = 0; nt < 4; nt++) {
            int c = cb + nt * 8 + 2 * t4;
            float b0 = bias[c], b1 = bias[c + 1];
            #pragma unroll
            for (int hrow = 0; hrow < 2; hrow++) {
                size_t R = mb + wm * 32 + mt * 16 + g + hrow * 8;
                float2 xv = *(const float2*)(g_xf + R * DM + c);
                float2 o;
                o.x = xv.x + acc[mt][nt][2 * hrow]     + b0;
                o.y = xv.y + acc[mt][nt][2 * hrow + 1] + b1;
                *(float2*)(out + R * DM + c) = o;
            }
        }
}

extern "C" void kernel_launch(void* const* d_in, const int* in_sizes, int n_in,
                              void* d_out, int out_size)
{
    const float* x      = (const float*)d_in[0];
    const float* ln1_g  = (const float*)d_in[1];
    const float* ln1_b  = (const float*)d_in[2];
    const float* qkv_w  = (const float*)d_in[3];
    const float* qkv_b  = (const float*)d_in[4];
    const float* proj_w = (const float*)d_in[5];
    const float* proj_b = (const float*)d_in[6];
    const float* lscale = (const float*)d_in[7];
    const float* ln2_g  = (const float*)d_in[8];
    const float* ln2_b  = (const float*)d_in[9];
    const float* ffn_w1 = (const float*)d_in[10];
    const float* ffn_b1 = (const float*)d_in[11];
    const float* ffn_w2 = (const float*)d_in[12];
    const float* ffn_b2 = (const float*)d_in[13];
    float* out = (float*)d_out;

    __nv_bfloat16 *gy, *gy2;
    cudaGetSymbolAddress((void**)&gy,  g_y);
    cudaGetSymbolAddress((void**)&gy2, g_y2);
    float* gxf;
    cudaGetSymbolAddress((void**)&gxf, g_xf);

    const int smG = SM_A_BYTES + SM_B_BYTES;        // 100352
    const int smQ = 8 * HSTR * 2;                   // 61568 (attn tiles)
    cudaFuncSetAttribute(k_qkv,  cudaFuncAttributeMaxDynamicSharedMemorySize, smG);
    cudaFuncSetAttribute(k_proj, cudaFuncAttributeMaxDynamicSharedMemorySize, smG);
    cudaFuncSetAttribute(k_ffn1, cudaFuncAttributeMaxDynamicSharedMemorySize, smG);
    cudaFuncSetAttribute(k_ffn2, cudaFuncAttributeMaxDynamicSharedMemorySize, smG);
    cudaFuncSetAttribute(attn_kernel, cudaFuncAttributeMaxDynamicSharedMemorySize, smQ);

    prep_pack<<<(WU32 + 255) / 256, 256>>>(qkv_w, proj_w, ffn_w1, ffn_w2);
    ln_kernel<<<NROWS / 8, 256>>>(x, gy, ln1_g, ln1_b);
    k_qkv <<<dim3(12, 1600), 256, smG>>>(qkv_b, lscale);
    attn_kernel<<<NSEQ, 256, smQ>>>();
    k_proj<<<dim3(4, 1600), 256, smG>>>(x, proj_b);
    ln_kernel<<<NROWS / 8, 256>>>(gxf, gy2, ln2_g, ln2_b);
    k_ffn1<<<dim3(16, 1600), 256, smG>>>(ffn_b1);
    k_ffn2<<<dim3(4, 1600), 256, smG>>>(ffn_b2, out);
}

// round 13
// speedup vs baseline: 2.0578x; 1.0206x over previous
#include <cuda_runtime.h>
#include <cuda_bf16.h>
#include <math.h>
#include <stdint.h>

#define NSEQ  8192
#define VTOK  25
#define NROWS 204800          // NSEQ * VTOK
#define DM    256
#define NH    8
#define HD    32
#define DF    1024
#define N3    768
#define LDC   136             // pipelined A-chunk row stride (halves)
#define LDT   40              // attn per-head tile row stride (halves)
#define HSTR  3848            // attn per-head smem stride

// packed bf16 fragment weights (uint32 words): [tile][kb32][lane][uint4]
#define BQ_OFF 0
#define BP_OFF 98304
#define B1_OFF 131072
#define B2_OFF 262144
#define WU32   393216

__device__ uint32_t       g_wb[WU32];
__device__ __nv_bfloat16  g_y  [(size_t)NROWS * DM];    // LN1 out
__device__ __nv_bfloat16  g_qkvh[(size_t)NROWS * N3];   // q-hat / k-hat / v (bf16)
__device__ __nv_bfloat16  g_att[(size_t)NROWS * DM];    // attention out
__device__ float          g_xf [(size_t)NROWS * DM];    // residual after proj (fp32)
__device__ __nv_bfloat16  g_y2 [(size_t)NROWS * DM];    // LN2 out
__device__ __nv_bfloat16  g_h  [(size_t)NROWS * DF];    // FFN hidden

__device__ __forceinline__ float gelu_exact(float v) {
    return 0.5f * v * (1.f + erff(v * 0.70710678118654752440f));
}
__device__ __forceinline__ uint32_t pack_bf2(float lo, float hi) {
    __nv_bfloat162 p;
    p.x = __float2bfloat16_rn(lo);
    p.y = __float2bfloat16_rn(hi);
    return *(uint32_t*)&p;
}

// ---- weight packing to bf16 m16n8k16 B-fragments ----
__global__ void prep_pack(const float* __restrict__ qkv_w, const float* __restrict__ proj_w,
                          const float* __restrict__ f1,    const float* __restrict__ f2) {
    int i = blockIdx.x * 256 + threadIdx.x;
    if (i >= WU32) return;
    int comp = i & 3, lane = (i >> 2) & 31;
    int g = lane >> 2, t4 = lane & 3;
    int klo = 2 * t4 + ((comp & 1) << 3) + ((comp >> 1) << 4);
    const float* W; int ldw, k, col;
    if (i < BP_OFF) {                         // QKV: 96 tiles x 8 kb
        int r2 = i >> 7;  int kb = r2 & 7, tile = r2 >> 3;
        col = tile * 8 + g; k = kb * 32 + klo; W = qkv_w; ldw = N3;
    } else if (i < B1_OFF) {                  // proj: 32 tiles x 8 kb
        int r2 = (i - BP_OFF) >> 7;  int kb = r2 & 7, tile = r2 >> 3;
        col = tile * 8 + g; k = kb * 32 + klo; W = proj_w; ldw = DM;
    } else if (i < B2_OFF) {                  // ffn1: 128 tiles x 8 kb
        int r2 = (i - B1_OFF) >> 7;  int kb = r2 & 7, tile = r2 >> 3;
        col = tile * 8 + g; k = kb * 32 + klo; W = f1; ldw = DF;
    } else {                                  // ffn2: 32 tiles x 32 kb (K=1024)
        int r2 = (i - B2_OFF) >> 7;  int kb = r2 & 31, tile = r2 >> 5;
        col = tile * 8 + g; k = kb * 32 + klo; W = f2; ldw = DM;
    }
    g_wb[i] = pack_bf2(W[(size_t)k * ldw + col], W[(size_t)(k + 1) * ldw + col]);
}

#define MMA_BF(D, A, B0, B1)                                                \
    asm("mma.sync.aligned.m16n8k16.row.col.f32.bf16.bf16.f32 "              \
        "{%0,%1,%2,%3}, {%4,%5,%6,%7}, {%8,%9}, {%0,%1,%2,%3};"             \
        : "+f"(D[0]), "+f"(D[1]), "+f"(D[2]), "+f"(D[3])                    \
        : "r"(A[0]), "r"(A[1]), "r"(A[2]), "r"(A[3]), "r"(B0), "r"(B1))

#define LDSM4(A, addr)                                                      \
    asm volatile("ldmatrix.sync.aligned.m8n8.x4.shared.b16 {%0,%1,%2,%3}, [%4];" \
        : "=r"(A[0]), "=r"(A[1]), "=r"(A[2]), "=r"(A[3]) : "r"(addr))

#define LDSM4T(A, addr)                                                     \
    asm volatile("ldmatrix.sync.aligned.m8n8.x4.trans.shared.b16 {%0,%1,%2,%3}, [%4];" \
        : "=r"(A[0]), "=r"(A[1]), "=r"(A[2]), "=r"(A[3]) : "r"(addr))

#define LDS128U(r0, r1, r2, r3, addr)                                       \
    asm volatile("ld.shared.v4.u32 {%0,%1,%2,%3}, [%4];"                    \
        : "=r"(r0), "=r"(r1), "=r"(r2), "=r"(r3) : "r"(addr))

__device__ __forceinline__ void cp_async16(uint32_t saddr, const void* g) {
    asm volatile("cp.async.cg.shared.global [%0], [%1], 16;" :: "r"(saddr), "l"(g) : "memory");
}
#define CP_COMMIT() asm volatile("cp.async.commit_group;" ::: "memory")
#define CP_WAIT0()  asm volatile("cp.async.wait_group 0;" ::: "memory")
#define CP_WAIT1()  asm volatile("cp.async.wait_group 1;" ::: "memory")

__device__ __forceinline__ uint32_t ldsm_addr(const __nv_bfloat16* base, int ldh, int lane) {
    return (uint32_t)__cvta_generic_to_shared(base + (lane & 15) * ldh + (lane >> 4) * 8);
}

// Warp computes 32 x NT*8 tile for one K-chunk; A via ldmatrix, B frags from smem.
template<int NT, int KB>
__device__ __forceinline__ void gemm_sm(uint32_t a0addr, uint32_t a1addr,
                                        uint32_t sBaddr, int tbase,
                                        float (&acc)[2][NT][4], int lane)
{
    #pragma unroll
    for (int kb = 0; kb < KB; kb++) {
        uint32_t A0[4], A1[4], A2[4], A3[4];
        LDSM4(A0, a0addr + kb * 64);
        LDSM4(A1, a1addr + kb * 64);
        LDSM4(A2, a0addr + kb * 64 + 32);
        LDSM4(A3, a1addr + kb * 64 + 32);
        #pragma unroll
        for (int nt = 0; nt < NT; nt++) {
            uint32_t b0, b1, b2, b3;
            LDS128U(b0, b1, b2, b3, sBaddr + (((tbase + nt) * KB + kb) * 32 + lane) * 16);
            MMA_BF(acc[0][nt], A0, b0, b1);
            MMA_BF(acc[1][nt], A1, b0, b1);
            MMA_BF(acc[0][nt], A2, b2, b3);
            MMA_BF(acc[1][nt], A3, b2, b3);
        }
    }
}

// ---- chunk loaders: A = 128 rows x 128 cols bf16; B = 8 tiles x 4 kb frags ----
__device__ __forceinline__ void load_chunkA(const __nv_bfloat16* __restrict__ Ag,
                                            size_t row0, int srow, int c,
                                            __nv_bfloat16* __restrict__ sAbuf, int tid)
{
    uint32_t sbase = (uint32_t)__cvta_generic_to_shared(sAbuf);
    #pragma unroll
    for (int i = 0; i < 8; i++) {
        int idx = tid + i * 256;
        int row = idx >> 4, c16 = idx & 15;
        cp_async16(sbase + (row * LDC + c16 * 8) * 2,
                   Ag + (row0 + row) * (size_t)srow + c * 128 + c16 * 8);
    }
}
template<int KBT>
__device__ __forceinline__ void load_chunkB(const uint4* __restrict__ Bbase, int c,
                                            uint32_t sBbuf, int tid)
{
    #pragma unroll
    for (int i = 0; i < 4; i++) {
        int idx = tid + i * 256;
        int t = idx >> 7, rem = idx & 127, kb = rem >> 5, ln = rem & 31;
        cp_async16(sBbuf + idx * 16,
                   Bbase + ((size_t)(t * KBT + c * 4 + kb) * 32 + ln));
    }
}

// ---- pipelined GEMM mainloop: KC chunks of K=128, double-buffered ----
template<int KC, int KBT>
__device__ __forceinline__ void gemm_pipe(const __nv_bfloat16* __restrict__ Ag,
                                          size_t mb, int srow,
                                          const uint4* __restrict__ Bbase,
                                          float (&acc)[2][4][4],
                                          __nv_bfloat16* sA, uint32_t sB0,
                                          int tid, int lane, int wm, int wn)
{
    __nv_bfloat16* sA0 = sA;
    __nv_bfloat16* sA1 = sA + 128 * LDC;
    load_chunkA(Ag, mb, srow, 0, sA0, tid);
    load_chunkB<KBT>(Bbase, 0, sB0, tid);
    CP_COMMIT();
    load_chunkA(Ag, mb, srow, 1, sA1, tid);
    load_chunkB<KBT>(Bbase, 1, sB0 + 16384, tid);
    CP_COMMIT();
    #pragma unroll
    for (int c = 0; c < KC; c++) {
        if (c < KC - 1) { CP_WAIT1(); } else { CP_WAIT0(); }
        __syncthreads();
        __nv_bfloat16* sAc = (c & 1) ? sA1 : sA0;
        uint32_t sBc = (c & 1) ? (sB0 + 16384) : sB0;
        uint32_t a0 = ldsm_addr(sAc + wm * 32 * LDC, LDC, lane);
        uint32_t a1 = a0 + 16 * LDC * 2;
        gemm_sm<4, 4>(a0, a1, sBc, wn * 4, acc, lane);
        if (c + 2 < KC) {
            __syncthreads();
            load_chunkA(Ag, mb, srow, c + 2, sAc, tid);
            load_chunkB<KBT>(Bbase, c + 2, sBc, tid);
            CP_COMMIT();
        }
    }
}

// ---- LayerNorm: fp32 rows -> bf16 rows ----
__device__ __forceinline__ void ln_row_bf(const float* __restrict__ src,
                                          __nv_bfloat16* __restrict__ dst,
                                          const float* __restrict__ gg,
                                          const float* __restrict__ bb, int lane)
{
    float v[8], s = 0.f, s2 = 0.f;
    #pragma unroll
    for (int j = 0; j < 8; j++) { v[j] = src[lane + 32 * j]; s += v[j]; s2 += v[j] * v[j]; }
    #pragma unroll
    for (int o = 16; o > 0; o >>= 1) {
        s  += __shfl_xor_sync(0xffffffffu, s,  o);
        s2 += __shfl_xor_sync(0xffffffffu, s2, o);
    }
    float mean = s * (1.f / DM);
    float var  = s2 * (1.f / DM) - mean * mean;
    float inv  = rsqrtf(var + 1e-5f);
    #pragma unroll
    for (int j = 0; j < 8; j++) {
        int c = lane + 32 * j;
        dst[c] = __float2bfloat16_rn((v[j] - mean) * inv * gg[c] + bb[c]);
    }
}

__global__ __launch_bounds__(256) void ln_kernel(const float* __restrict__ src,
                                                 __nv_bfloat16* __restrict__ dst,
                                                 const float* __restrict__ gg,
                                                 const float* __restrict__ bb)
{
    int row  = blockIdx.x * 8 + (threadIdx.x >> 5);
    int lane = threadIdx.x & 31;
    ln_row_bf(src + (size_t)row * DM, dst + (size_t)row * DM, gg, bb, lane);
}

#define SM_PIPE 102400    // 2*(128*LDC*2) + 2*16384

#define GEMM_PRO()                                                          \
    extern __shared__ __nv_bfloat16 sA[];                                   \
    uint32_t sB0 = (uint32_t)__cvta_generic_to_shared(sA) + 2 * 128 * LDC * 2; \
    const int tid = threadIdx.x, lane = tid & 31;                           \
    const int wid = tid >> 5, wm = wid >> 1, wn = wid & 1;                  \
    const int g = lane >> 2, t4 = lane & 3;                                 \
    const int ntblk = blockIdx.x;                                           \
    const size_t mb = (size_t)blockIdx.y * 128;                             \
    float acc[2][4][4];                                                     \
    _Pragma("unroll") for (int mt = 0; mt < 2; mt++)                        \
    _Pragma("unroll") for (int nt = 0; nt < 4; nt++)                        \
    _Pragma("unroll") for (int e = 0; e < 4; e++) acc[mt][nt][e] = 0.f;

// ---- QKV GEMM + fused q/k L2-normalization -> g_qkvh (bf16). grid (12, 1600) ----
__global__ __launch_bounds__(256, 2) void k_qkv(const float* __restrict__ bias,
                                                const float* __restrict__ lscale)
{
    GEMM_PRO();
    gemm_pipe<2, 8>(g_y, mb, DM, (const uint4*)g_wb + BQ_OFF / 4 + (size_t)ntblk * 2048,
                    acc, sA, sB0, tid, lane, wm, wn);

    const int cb = ntblk * 64 + wn * 32;
    const bool donorm = (ntblk < 8);
    float qmul = 1.f;
    if (ntblk < 4)
        qmul = expf(fminf(lscale[(cb & 255) >> 5], 4.6051701859880913680f))
             * 0.17677669529663688110f;     // sc_h / sqrt(32)

    float bv[8];
    #pragma unroll
    for (int nt = 0; nt < 4; nt++) {
        bv[2 * nt]     = bias[cb + nt * 8 + 2 * t4];
        bv[2 * nt + 1] = bias[cb + nt * 8 + 2 * t4 + 1];
    }

    #pragma unroll
    for (int mt = 0; mt < 2; mt++)
        #pragma unroll
        for (int hrow = 0; hrow < 2; hrow++) {
            float v[8];
            #pragma unroll
            for (int nt = 0; nt < 4; nt++) {
                v[2 * nt]     = acc[mt][nt][2 * hrow]     + bv[2 * nt];
                v[2 * nt + 1] = acc[mt][nt][2 * hrow + 1] + bv[2 * nt + 1];
            }
            float s = qmul;
            if (donorm) {
                float ssq = 0.f;
                #pragma unroll
                for (int e = 0; e < 8; e++) ssq = fmaf(v[e], v[e], ssq);
                ssq += __shfl_xor_sync(0xffffffffu, ssq, 1);
                ssq += __shfl_xor_sync(0xffffffffu, ssq, 2);
                s = qmul / fmaxf(sqrtf(ssq), 1e-12f);
            }
            size_t R = mb + wm * 32 + mt * 16 + g + hrow * 8;
            #pragma unroll
            for (int nt = 0; nt < 4; nt++)
                *(uint32_t*)(g_qkvh + R * N3 + cb + nt * 8 + 2 * t4) =
                    pack_bf2(v[2 * nt] * s, v[2 * nt + 1] * s);
        }
}

// ---- attention: block = sequence, warp = head; pure MMA ----
__global__ __launch_bounds__(256, 2) void attn_kernel()
{
    extern __shared__ __nv_bfloat16 smt[];
    const int tid = threadIdx.x, lane = tid & 31, h = tid >> 5;
    const int g = lane >> 2, t4 = lane & 3;
    const size_t seq = blockIdx.x;

    const uint4* src = (const uint4*)(g_qkvh + seq * (size_t)(VTOK * N3));
    #pragma unroll
    for (int it = 0; it < 10; it++) {
        int idx = tid + it * 256;
        if (idx < 2400) {
            int row = idx / 96, c8 = idx - row * 96;
            int col = c8 * 8;
            int region = col >> 8;              // 0=q 1=k 2=v
            int head = (col & 255) >> 5;
            *(uint4*)(smt + head * HSTR + region * (32 * LDT) + row * LDT + (col & 31)) = src[idx];
        }
    }
    if (tid < 224) {
        int head = tid / 28, i2 = tid % 28;
        uint4 z = make_uint4(0, 0, 0, 0);
        *(uint4*)(smt + head * HSTR + 2 * (32 * LDT) + (25 + (i2 >> 2)) * LDT + (i2 & 3) * 8) = z;
    }
    __syncthreads();

    __nv_bfloat16* sq = smt + h * HSTR;
    __nv_bfloat16* sk = sq + 32 * LDT;
    __nv_bfloat16* sv = sk + 32 * LDT;

    uint32_t qb  = (uint32_t)__cvta_generic_to_shared(sq);
    uint32_t kbb = (uint32_t)__cvta_generic_to_shared(sk);
    uint32_t vbb = (uint32_t)__cvta_generic_to_shared(sv);

    uint32_t aq[2][2][4];
    #pragma unroll
    for (int mt = 0; mt < 2; mt++)
        #pragma unroll
        for (int c = 0; c < 2; c++) {
            uint32_t addr = qb + (mt * 16 + (lane & 15)) * (LDT * 2) + (lane >> 4) * 16 + c * 32;
            LDSM4(aq[mt][c], addr);
        }
    uint32_t bk[4][4];
    #pragma unroll
    for (int nt = 0; nt < 4; nt++) {
        uint32_t addr = kbb + (nt * 8 + (lane & 7)) * (LDT * 2) + (lane >> 3) * 16;
        LDSM4(bk[nt], addr);
    }

    float accl[2][4][4];
    #pragma unroll
    for (int mt = 0; mt < 2; mt++)
        #pragma unroll
        for (int nt = 0; nt < 4; nt++)
            #pragma unroll
            for (int e = 0; e < 4; e++) accl[mt][nt][e] = 0.f;
    #pragma unroll
    for (int mt = 0; mt < 2; mt++)
        #pragma unroll
        for (int nt = 0; nt < 4; nt++) {
            MMA_BF(accl[mt][nt], aq[mt][0], bk[nt][0], bk[nt][1]);
            MMA_BF(accl[mt][nt], aq[mt][1], bk[nt][2], bk[nt][3]);
        }

    #pragma unroll
    for (int mt = 0; mt < 2; mt++)
        #pragma unroll
        for (int hrow = 0; hrow < 2; hrow++) {
            float m = -1e30f;
            #pragma unroll
            for (int nt = 0; nt < 4; nt++)
                #pragma unroll
                for (int e = 0; e < 2; e++) {
                    int c = nt * 8 + 2 * t4 + e;
                    float vl = (c < VTOK) ? accl[mt][nt][2 * hrow + e] : -1e30f;
                    accl[mt][nt][2 * hrow + e] = vl;
                    m = fmaxf(m, vl);
                }
            m = fmaxf(m, __shfl_xor_sync(0xffffffffu, m, 1));
            m = fmaxf(m, __shfl_xor_sync(0xffffffffu, m, 2));
            float s = 0.f;
            #pragma unroll
            for (int nt = 0; nt < 4; nt++)
                #pragma unroll
                for (int e = 0; e < 2; e++) {
                    float p = __expf(accl[mt][nt][2 * hrow + e] - m);
                    accl[mt][nt][2 * hrow + e] = p;
                    s += p;
                }
            s += __shfl_xor_sync(0xffffffffu, s, 1);
            s += __shfl_xor_sync(0xffffffffu, s, 2);
            float rs = 1.f / s;
            #pragma unroll
            for (int nt = 0; nt < 4; nt++)
                #pragma unroll
                for (int e = 0; e < 2; e++) accl[mt][nt][2 * hrow + e] *= rs;
        }

    uint32_t pa[2][2][4];
    #pragma unroll
    for (int mt = 0; mt < 2; mt++)
        #pragma unroll
        for (int c = 0; c < 2; c++) {
            pa[mt][c][0] = pack_bf2(accl[mt][2*c  ][0], accl[mt][2*c  ][1]);
            pa[mt][c][1] = pack_bf2(accl[mt][2*c  ][2], accl[mt][2*c  ][3]);
            pa[mt][c][2] = pack_bf2(accl[mt][2*c+1][0], accl[mt][2*c+1][1]);
            pa[mt][c][3] = pack_bf2(accl[mt][2*c+1][2], accl[mt][2*c+1][3]);
        }

    uint32_t bv[2][2][4];
    #pragma unroll
    for (int c = 0; c < 2; c++)
        #pragma unroll
        for (int np = 0; np < 2; np++) {
            uint32_t addr = vbb + (c * 16 + ((lane >> 3) & 1) * 8 + (lane & 7)) * (LDT * 2)
                          + np * 32 + (lane >> 4) * 16;
            LDSM4T(bv[c][np], addr);
        }

    float acco[2][4][4];
    #pragma unroll
    for (int mt = 0; mt < 2; mt++)
        #pragma unroll
        for (int nt = 0; nt < 4; nt++)
            #pragma unroll
            for (int e = 0; e < 4; e++) acco[mt][nt][e] = 0.f;
    #pragma unroll
    for (int mt = 0; mt < 2; mt++)
        #pragma unroll
        for (int nt = 0; nt < 4; nt++) {
            int np = nt >> 1, hi = (nt & 1) * 2;
            MMA_BF(acco[mt][nt], pa[mt][0], bv[0][np][hi], bv[0][np][hi + 1]);
            MMA_BF(acco[mt][nt], pa[mt][1], bv[1][np][hi], bv[1][np][hi + 1]);
        }

    #pragma unroll
    for (int mt = 0; mt < 2; mt++)
        #pragma unroll
        for (int hrow = 0; hrow < 2; hrow++) {
            int token = mt * 16 + g + hrow * 8;
            if (token < VTOK) {
                __nv_bfloat16* og = g_att + (seq * VTOK + token) * DM + h * HD;
                #pragma unroll
                for (int nt = 0; nt < 4; nt++)
                    *(uint32_t*)(og + nt * 8 + 2 * t4) =
                        pack_bf2(acco[mt][nt][2 * hrow], acco[mt][nt][2 * hrow + 1]);
            }
        }
}

// ---- proj GEMM + residual -> g_xf (fp32). grid (4, 1600) ----
__global__ __launch_bounds__(256, 2) void k_proj(const float* __restrict__ x,
                                                 const float* __restrict__ bias)
{
    GEMM_PRO();
    gemm_pipe<2, 8>(g_att, mb, DM, (const uint4*)g_wb + BP_OFF / 4 + (size_t)ntblk * 2048,
                    acc, sA, sB0, tid, lane, wm, wn);
    const int cb = ntblk * 64 + wn * 32;
    #pragma unroll
    for (int mt = 0; mt < 2; mt++)
        #pragma unroll
        for (int nt = 0; nt < 4; nt++) {
            int c = cb + nt * 8 + 2 * t4;
            float b0 = bias[c], b1 = bias[c + 1];
            #pragma unroll
            for (int hrow = 0; hrow < 2; hrow++) {
                size_t R = mb + wm * 32 + mt * 16 + g + hrow * 8;
                float2 xv = *(const float2*)(x + R * DM + c);
                float2 o;
                o.x = xv.x + acc[mt][nt][2 * hrow]     + b0;
                o.y = xv.y + acc[mt][nt][2 * hrow + 1] + b1;
                *(float2*)(g_xf + R * DM + c) = o;
            }
        }
}

// ---- FFN1 GEMM + gelu -> g_h (bf16). grid (16, 1600) ----
__global__ __launch_bounds__(256, 2) void k_ffn1(const float* __restrict__ bias)
{
    GEMM_PRO();
    gemm_pipe<2, 8>(g_y2, mb, DM, (const uint4*)g_wb + B1_OFF / 4 + (size_t)ntblk * 2048,
                    acc, sA, sB0, tid, lane, wm, wn);
    const int cb = ntblk * 64 + wn * 32;
    #pragma unroll
    for (int mt = 0; mt < 2; mt++)
        #pragma unroll
        for (int nt = 0; nt < 4; nt++) {
            int c = cb + nt * 8 + 2 * t4;
            float b0 = bias[c], b1 = bias[c + 1];
            #pragma unroll
            for (int hrow = 0; hrow < 2; hrow++) {
                size_t R = mb + wm * 32 + mt * 16 + g + hrow * 8;
                *(uint32_t*)(g_h + R * DF + c) =
                    pack_bf2(gelu_exact(acc[mt][nt][2 * hrow] + b0),
                             gelu_exact(acc[mt][nt][2 * hrow + 1] + b1));
            }
        }
}

// ---- FFN2 GEMM + residual -> out (fp32). grid (4, 1600) ----
__global__ __launch_bounds__(256, 2) void k_ffn2(const float* __restrict__ bias,
                                                 float* __restrict__ out)
{
    GEMM_PRO();
    gemm_pipe<8, 32>(g_h, mb, DF, (const uint4*)g_wb + B2_OFF / 4 + (size_t)ntblk * 8192,
                     acc, sA, sB0, tid, lane, wm, wn);
    const int cb = ntblk * 64 + wn * 32;
    #pragma unroll
    for (int mt = 0; mt < 2; mt++)
        #pragma unroll
        for (int nt = 0; nt < 4; nt++) {
            int c = cb + nt * 8 + 2 * t4;
            float b0 = bias[c], b1 = bias[c + 1];
            #pragma unroll
            for (int hrow = 0; hrow < 2; hrow++) {
                size_t R = mb + wm * 32 + mt * 16 + g + hrow * 8;
                float2 xv = *(const float2*)(g_xf + R * DM + c);
                float2 o;
                o.x = xv.x + acc[mt][nt][2 * hrow]     + b0;
                o.y = xv.y + acc[mt][nt][2 * hrow + 1] + b1;
                *(float2*)(out + R * DM + c) = o;
            }
        }
}

extern "C" void kernel_launch(void* const* d_in, const int* in_sizes, int n_in,
                              void* d_out, int out_size)
{
    const float* x      = (const float*)d_in[0];
    const float* ln1_g  = (const float*)d_in[1];
    const float* ln1_b  = (const float*)d_in[2];
    const float* qkv_w  = (const float*)d_in[3];
    const float* qkv_b  = (const float*)d_in[4];
    const float* proj_w = (const float*)d_in[5];
    const float* proj_b = (const float*)d_in[6];
    const float* lscale = (const float*)d_in[7];
    const float* ln2_g  = (const float*)d_in[8];
    const float* ln2_b  = (const float*)d_in[9];
    const float* ffn_w1 = (const float*)d_in[10];
    const float* ffn_b1 = (const float*)d_in[11];
    const float* ffn_w2 = (const float*)d_in[12];
    const float* ffn_b2 = (const float*)d_in[13];
    float* out = (float*)d_out;

    __nv_bfloat16 *gy, *gy2;
    cudaGetSymbolAddress((void**)&gy,  g_y);
    cudaGetSymbolAddress((void**)&gy2, g_y2);
    float* gxf;
    cudaGetSymbolAddress((void**)&gxf, g_xf);

    const int smQ = 8 * HSTR * 2;                   // 61568 (attn tiles)
    cudaFuncSetAttribute(k_qkv,  cudaFuncAttributeMaxDynamicSharedMemorySize, SM_PIPE);
    cudaFuncSetAttribute(k_proj, cudaFuncAttributeMaxDynamicSharedMemorySize, SM_PIPE);
    cudaFuncSetAttribute(k_ffn1, cudaFuncAttributeMaxDynamicSharedMemorySize, SM_PIPE);
    cudaFuncSetAttribute(k_ffn2, cudaFuncAttributeMaxDynamicSharedMemorySize, SM_PIPE);
    cudaFuncSetAttribute(attn_kernel, cudaFuncAttributeMaxDynamicSharedMemorySize, smQ);

    prep_pack<<<(WU32 + 255) / 256, 256>>>(qkv_w, proj_w, ffn_w1, ffn_w2);
    ln_kernel<<<NROWS / 8, 256>>>(x, gy, ln1_g, ln1_b);
    k_qkv <<<dim3(12, 1600), 256, SM_PIPE>>>(qkv_b, lscale);
    attn_kernel<<<NSEQ, 256, smQ>>>();
    k_proj<<<dim3(4, 1600), 256, SM_PIPE>>>(x, proj_b);
    ln_kernel<<<NROWS / 8, 256>>>(gxf, gy2, ln2_g, ln2_b);
    k_ffn1<<<dim3(16, 1600), 256, SM_PIPE>>>(ffn_b1);
    k_ffn2<<<dim3(4, 1600), 256, SM_PIPE>>>(ffn_b2, out);
}